// round 1
// baseline (speedup 1.0000x reference)
#include <cuda_runtime.h>
#include <math.h>

// ---------------- problem constants ----------------
#define B_  4
#define T_  1024
#define D_  768
#define H_  12
#define HD_ 64
#define L_  6
#define V_  50257
#define NT  4096          // B_*T_
#define FF  3072          // 4*D_

// ---------------- scratch (static device globals; no allocation) ----------------
__device__ float g_x  [NT * D_];
__device__ float g_h  [NT * D_];
__device__ float g_q  [NT * D_];
__device__ float g_k  [NT * D_];
__device__ float g_v  [NT * D_];
__device__ float g_att[NT * D_];
__device__ float g_scores[48 * 1024 * 1024];   // B_*H_*T_*T_ = 50331648
__device__ float g_mlp[NT * FF];
__device__ float g_nll[NT];

// ---------------- GEMM: C = act(alpha*A@B(+^T) + bias + R) ----------------
// BM=BN=128, BK=8, 256 threads, 8x8 microtile per thread.
#define BM 128
#define BN 128
#define BK 8

__global__ void gemm_kernel(const float* __restrict__ A, const float* __restrict__ B,
                            const float* __restrict__ bias, const float* __restrict__ R,
                            float* __restrict__ C,
                            int M, int N, int K, int lda, int ldb, int ldc,
                            long sAb, long sAh, long sBb, long sBh, long sCb, long sCh,
                            int batchH, float alpha, int transB, int act)
{
    __shared__ __align__(16) float As[BK][BM + 4];
    __shared__ __align__(16) float Bs[BK][BN + 4];

    int z  = blockIdx.z;
    int bz = z / batchH, hz = z % batchH;
    A += (long)bz * sAb + (long)hz * sAh;
    B += (long)bz * sBb + (long)hz * sBh;
    C += (long)bz * sCb + (long)hz * sCh;
    if (R) R += (long)bz * sCb + (long)hz * sCh;

    int m0 = blockIdx.y * BM;
    int n0 = blockIdx.x * BN;
    int tid = threadIdx.x;
    int tx = tid & 15;        // N direction (16)
    int ty = tid >> 4;        // M direction (16)

    float acc[8][8];
#pragma unroll
    for (int i = 0; i < 8; i++)
#pragma unroll
        for (int j = 0; j < 8; j++) acc[i][j] = 0.f;

    for (int k0 = 0; k0 < K; k0 += BK) {
        // load A tile [BM x BK] -> As[k][m]   (K is always a multiple of 8 here)
#pragma unroll
        for (int i = 0; i < 4; i++) {
            int idx = tid + i * 256;
            int kk = idx & 7, mm = idx >> 3;
            int gm = m0 + mm;
            As[kk][mm] = (gm < M) ? A[(long)gm * lda + (k0 + kk)] : 0.f;
        }
        // load B tile
        if (!transB) {
#pragma unroll
            for (int i = 0; i < 4; i++) {
                int idx = tid + i * 256;
                int nn = idx & 127, kk = idx >> 7;
                int gn = n0 + nn;
                Bs[kk][nn] = (gn < N) ? B[(long)(k0 + kk) * ldb + gn] : 0.f;
            }
        } else {
#pragma unroll
            for (int i = 0; i < 4; i++) {
                int idx = tid + i * 256;
                int kk = idx & 7, nn = idx >> 3;
                int gn = n0 + nn;
                Bs[kk][nn] = (gn < N) ? B[(long)gn * ldb + (k0 + kk)] : 0.f;
            }
        }
        __syncthreads();

#pragma unroll
        for (int kk = 0; kk < BK; kk++) {
            float4 a0 = *(const float4*)&As[kk][ty * 8];
            float4 a1 = *(const float4*)&As[kk][ty * 8 + 4];
            float4 b0 = *(const float4*)&Bs[kk][tx * 8];
            float4 b1 = *(const float4*)&Bs[kk][tx * 8 + 4];
            float ra[8] = {a0.x, a0.y, a0.z, a0.w, a1.x, a1.y, a1.z, a1.w};
            float rb[8] = {b0.x, b0.y, b0.z, b0.w, b1.x, b1.y, b1.z, b1.w};
#pragma unroll
            for (int i = 0; i < 8; i++)
#pragma unroll
                for (int j = 0; j < 8; j++)
                    acc[i][j] += ra[i] * rb[j];
        }
        __syncthreads();
    }

#pragma unroll
    for (int i = 0; i < 8; i++) {
        int gm = m0 + ty * 8 + i;
        if (gm >= M) continue;
#pragma unroll
        for (int j = 0; j < 8; j++) {
            int gn = n0 + tx * 8 + j;
            if (gn >= N) continue;
            float v = acc[i][j] * alpha;
            if (bias) v += bias[gn];
            if (R)    v += R[(long)gm * ldc + gn];
            if (act)  v = 0.5f * v * (1.f + erff(v * 0.70710678118654752f));
            C[(long)gm * ldc + gn] = v;
        }
    }
}

// ---------------- embedding ----------------
__global__ void embed_kernel(const int* __restrict__ idx, const float* __restrict__ tok,
                             const float* __restrict__ pos, float* __restrict__ x)
{
    long i = (long)blockIdx.x * 256 + threadIdx.x;
    if (i >= (long)NT * D_) return;
    int d = (int)(i % D_);
    long row = i / D_;
    int t = (int)(row % T_);
    x[i] = tok[(long)idx[row] * D_ + d] + pos[(long)t * D_ + d];
}

// ---------------- layernorm (one block per row) ----------------
__global__ void layernorm_kernel(const float* __restrict__ x, const float* __restrict__ w,
                                 const float* __restrict__ b, float* __restrict__ y)
{
    int r = blockIdx.x;
    const float* xr = x + (long)r * D_;
    float* yr = y + (long)r * D_;
    __shared__ float s1[256], s2[256];
    int tid = threadIdx.x;
    float a = 0.f, sq = 0.f;
    for (int i = tid; i < D_; i += 256) { float v = xr[i]; a += v; sq += v * v; }
    s1[tid] = a; s2[tid] = sq; __syncthreads();
    for (int s = 128; s > 0; s >>= 1) {
        if (tid < s) { s1[tid] += s1[tid + s]; s2[tid] += s2[tid + s]; }
        __syncthreads();
    }
    float mu = s1[0] * (1.f / D_);
    float var = s2[0] * (1.f / D_) - mu * mu;
    float rstd = rsqrtf(var + 1e-5f);
    for (int i = tid; i < D_; i += 256)
        yr[i] = (xr[i] - mu) * rstd * w[i] + b[i];
}

// ---------------- causal softmax over scores rows ----------------
__global__ void softmax_causal_kernel(float* __restrict__ scores)
{
    int r = blockIdx.x;               // 0 .. B_*H_*T_-1
    int q = r & (T_ - 1);
    float* row = scores + (long)r * T_;
    int len = q + 1;
    __shared__ float red[256];
    int tid = threadIdx.x;

    float m = -1e30f;
    for (int i = tid; i < len; i += 256) m = fmaxf(m, row[i]);
    red[tid] = m; __syncthreads();
    for (int s = 128; s > 0; s >>= 1) { if (tid < s) red[tid] = fmaxf(red[tid], red[tid + s]); __syncthreads(); }
    m = red[0]; __syncthreads();

    float sum = 0.f;
    for (int i = tid; i < len; i += 256) sum += expf(row[i] - m);
    red[tid] = sum; __syncthreads();
    for (int s = 128; s > 0; s >>= 1) { if (tid < s) red[tid] += red[tid + s]; __syncthreads(); }
    float inv = 1.f / red[0];

    for (int i = tid; i < T_; i += 256)
        row[i] = (i < len) ? expf(row[i] - m) * inv : 0.f;
}

// ---------------- NLL stage 1: per-row lse - logit[target] ----------------
__global__ void nll_kernel(const float* __restrict__ logits, const int* __restrict__ targets,
                           float* __restrict__ nll)
{
    int r = blockIdx.x;
    const float* row = logits + (long)r * V_;
    __shared__ float red[256];
    int tid = threadIdx.x;

    float m = -1e30f;
    for (int i = tid; i < V_; i += 256) m = fmaxf(m, row[i]);
    red[tid] = m; __syncthreads();
    for (int s = 128; s > 0; s >>= 1) { if (tid < s) red[tid] = fmaxf(red[tid], red[tid + s]); __syncthreads(); }
    m = red[0]; __syncthreads();

    float sum = 0.f;
    for (int i = tid; i < V_; i += 256) sum += expf(row[i] - m);
    red[tid] = sum; __syncthreads();
    for (int s = 128; s > 0; s >>= 1) { if (tid < s) red[tid] += red[tid + s]; __syncthreads(); }

    if (tid == 0) {
        float lse = m + logf(red[0]);
        nll[r] = lse - row[targets[r]];
    }
}

// ---------------- NLL stage 2: mean ----------------
__global__ void loss_reduce_kernel(const float* __restrict__ nll, float* __restrict__ out)
{
    __shared__ float red[256];
    int tid = threadIdx.x;
    float a = 0.f;
    for (int i = tid; i < NT; i += 256) a += nll[i];
    red[tid] = a; __syncthreads();
    for (int s = 128; s > 0; s >>= 1) { if (tid < s) red[tid] += red[tid + s]; __syncthreads(); }
    if (tid == 0) out[0] = red[0] * (1.f / NT);
}

// ---------------- host-side helpers ----------------
static inline void launch_gemm(const float* A, const float* B, const float* bias, const float* R,
                               float* C, int M, int N, int K, int lda, int ldb, int ldc,
                               long sAb, long sAh, long sBb, long sBh, long sCb, long sCh,
                               int batch, int batchH, float alpha, int transB, int act)
{
    dim3 grid((N + BN - 1) / BN, (M + BM - 1) / BM, batch);
    gemm_kernel<<<grid, 256>>>(A, B, bias, R, C, M, N, K, lda, ldb, ldc,
                               sAb, sAh, sBb, sBh, sCb, sCh, batchH, alpha, transB, act);
}

extern "C" void kernel_launch(void* const* d_in, const int* in_sizes, int n_in,
                              void* d_out, int out_size)
{
    const float* tok_emb = (const float*)d_in[0];
    const float* pos_emb = (const float*)d_in[1];
    const float* ln1_w   = (const float*)d_in[2];
    const float* ln1_b   = (const float*)d_in[3];
    const float* ln2_w   = (const float*)d_in[4];
    const float* ln2_b   = (const float*)d_in[5];
    const float* wq      = (const float*)d_in[6];
    const float* wk      = (const float*)d_in[7];
    const float* wv      = (const float*)d_in[8];
    const float* wproj   = (const float*)d_in[9];
    const float* bproj   = (const float*)d_in[10];
    const float* w1      = (const float*)d_in[11];
    const float* b1      = (const float*)d_in[12];
    const float* w2      = (const float*)d_in[13];
    const float* b2      = (const float*)d_in[14];
    const float* lnf_w   = (const float*)d_in[15];
    const float* lnf_b   = (const float*)d_in[16];
    const float* lm_w    = (const float*)d_in[17];
    const float* lm_b    = (const float*)d_in[18];
    const int*   indexp  = (const int*)d_in[19];
    const int*   targets = (const int*)d_in[20];

    float* out = (float*)d_out;

    float *x, *h, *q, *k, *v, *att, *scores, *mlp, *nll;
    cudaGetSymbolAddress((void**)&x,      g_x);
    cudaGetSymbolAddress((void**)&h,      g_h);
    cudaGetSymbolAddress((void**)&q,      g_q);
    cudaGetSymbolAddress((void**)&k,      g_k);
    cudaGetSymbolAddress((void**)&v,      g_v);
    cudaGetSymbolAddress((void**)&att,    g_att);
    cudaGetSymbolAddress((void**)&scores, g_scores);
    cudaGetSymbolAddress((void**)&mlp,    g_mlp);
    cudaGetSymbolAddress((void**)&nll,    g_nll);

    // x = tok_emb[index] + pos_emb
    {
        long total = (long)NT * D_;
        embed_kernel<<<(int)((total + 255) / 256), 256>>>(indexp, tok_emb, pos_emb, x);
    }

    const float scale = 1.0f / 8.0f;   // HD^-0.5 = 1/sqrt(64)

    for (int l = 0; l < L_; l++) {
        const float* wq_l = wq + (long)l * D_ * D_;
        const float* wk_l = wk + (long)l * D_ * D_;
        const float* wv_l = wv + (long)l * D_ * D_;
        const float* wp_l = wproj + (long)l * D_ * D_;
        const float* bp_l = bproj + (long)l * D_;
        const float* w1_l = w1 + (long)l * D_ * FF;
        const float* b1_l = b1 + (long)l * FF;
        const float* w2_l = w2 + (long)l * FF * D_;
        const float* b2_l = b2 + (long)l * D_;

        // h = LN1(x)
        layernorm_kernel<<<NT, 256>>>(x, ln1_w + (long)l * D_, ln1_b + (long)l * D_, h);

        // q,k,v = h @ W   [4096,768]x[768,768]
        launch_gemm(h, wq_l, nullptr, nullptr, q, NT, D_, D_, D_, D_, D_,
                    0, 0, 0, 0, 0, 0, 1, 1, 1.f, 0, 0);
        launch_gemm(h, wk_l, nullptr, nullptr, k, NT, D_, D_, D_, D_, D_,
                    0, 0, 0, 0, 0, 0, 1, 1, 1.f, 0, 0);
        launch_gemm(h, wv_l, nullptr, nullptr, v, NT, D_, D_, D_, D_, D_,
                    0, 0, 0, 0, 0, 0, 1, 1, 1.f, 0, 0);

        // scores[b,h,q,k] = scale * Q Kt   (batched over b,h: batch=48, batchH=12)
        launch_gemm(q, k, nullptr, nullptr, scores,
                    T_, T_, HD_, D_, D_, T_,
                    (long)T_ * D_, HD_,            // A strides (b, h)
                    (long)T_ * D_, HD_,            // B strides
                    (long)H_ * T_ * T_, (long)T_ * T_,   // C strides
                    B_ * H_, H_, scale, 1, 0);

        // causal softmax
        softmax_causal_kernel<<<B_ * H_ * T_, 256>>>(scores);

        // att[b,q,h,:] = wei @ V
        launch_gemm(scores, v, nullptr, nullptr, att,
                    T_, HD_, T_, T_, D_, D_,
                    (long)H_ * T_ * T_, (long)T_ * T_,
                    (long)T_ * D_, HD_,
                    (long)T_ * D_, HD_,
                    B_ * H_, H_, 1.f, 0, 0);

        // x = x + att @ wproj + bproj   (in-place, residual fused)
        launch_gemm(att, wp_l, bp_l, x, x, NT, D_, D_, D_, D_, D_,
                    0, 0, 0, 0, 0, 0, 1, 1, 1.f, 0, 0);

        // h = LN2(x)
        layernorm_kernel<<<NT, 256>>>(x, ln2_w + (long)l * D_, ln2_b + (long)l * D_, h);

        // mlp = gelu(h @ w1 + b1)
        launch_gemm(h, w1_l, b1_l, nullptr, mlp, NT, FF, D_, D_, FF, FF,
                    0, 0, 0, 0, 0, 0, 1, 1, 1.f, 0, 1);

        // x = x + mlp @ w2 + b2
        launch_gemm(mlp, w2_l, b2_l, x, x, NT, D_, FF, FF, D_, D_,
                    0, 0, 0, 0, 0, 0, 1, 1, 1.f, 0, 0);
    }

    // h = LNf(x)
    layernorm_kernel<<<NT, 256>>>(x, lnf_w, lnf_b, h);

    // logits = h @ lm_w + lm_b  -> d_out
    long logits_elems = (long)NT * V_;
    if ((long)out_size >= logits_elems) {
        launch_gemm(h, lm_w, lm_b, nullptr, out, NT, V_, D_, D_, V_, V_,
                    0, 0, 0, 0, 0, 0, 1, 1, 1.f, 0, 0);

        // loss
        nll_kernel<<<NT, 256>>>(out, targets, nll);
        if ((long)out_size >= logits_elems + 1) {
            loss_reduce_kernel<<<1, 256>>>(nll, out + logits_elems);
        }
    }
}

// round 2
// speedup vs baseline: 1.9397x; 1.9397x over previous
#include <cuda_runtime.h>
#include <math.h>
#include <stdint.h>

// ---------------- problem constants ----------------
#define B_  4
#define T_  1024
#define D_  768
#define H_  12
#define HD_ 64
#define L_  6
#define V_  50257
#define VPAD 50304        // V padded to multiple of 128
#define NT  4096          // B_*T_
#define FF  3072          // 4*D_

// ---------------- scratch (static device globals; no allocation) ----------------
__device__ float g_x  [NT * D_];
__device__ float g_h  [NT * D_];
__device__ float g_q  [NT * D_];
__device__ float g_k  [NT * D_];
__device__ float g_v  [NT * D_];
__device__ float g_att[NT * D_];
__device__ float g_scores[48 * 1024 * 1024];   // B_*H_*T_*T_
__device__ float g_mlp[NT * FF];
__device__ float g_nll[NT];
__device__ float g_lmw_pad[(size_t)D_ * VPAD]; // padded lm_w for vector loads

// ---------------- tf32 helpers ----------------
__device__ __forceinline__ uint32_t f2tf32(float x) {
    uint32_t y;
    asm("cvt.rna.tf32.f32 %0, %1;" : "=r"(y) : "f"(x));
    return y;
}

__device__ __forceinline__ void mma_tf32(float* c, const uint32_t* a, const uint32_t* b) {
    asm volatile(
        "mma.sync.aligned.m16n8k8.row.col.f32.tf32.tf32.f32 "
        "{%0,%1,%2,%3},{%4,%5,%6,%7},{%8,%9},{%0,%1,%2,%3};"
        : "+f"(c[0]), "+f"(c[1]), "+f"(c[2]), "+f"(c[3])
        : "r"(a[0]), "r"(a[1]), "r"(a[2]), "r"(a[3]), "r"(b[0]), "r"(b[1]));
}

// ---------------- TF32 GEMM: C = act(alpha*A@B(^T) + bias + R) ----------------
// BM=128, BN=128, BK=16; 256 threads = 8 warps (4 in M x 2 in N), warp tile 32x64.
#define BM 128
#define BN 128
#define BK 16
#define LDA_S 20    // As[m][k] pad: conflict-free fragment loads
#define LDB_S 136   // Bs[k][n] pad: conflict-free fragment loads

__global__ __launch_bounds__(256)
void gemm_tf32_kernel(const float* __restrict__ A, const float* __restrict__ B,
                      const float* __restrict__ bias, const float* __restrict__ R,
                      float* __restrict__ C,
                      int M, int N, int Nload, int K, int lda, int ldb, int ldc,
                      long sAb, long sAh, long sBb, long sBh, long sCb, long sCh,
                      int batchH, float alpha, int transB, int act)
{
    __shared__ uint32_t As[BM * LDA_S];
    __shared__ uint32_t Bs[BK * LDB_S];

    int z  = blockIdx.z;
    int bz = z / batchH, hz = z % batchH;
    A += (long)bz * sAb + (long)hz * sAh;
    B += (long)bz * sBb + (long)hz * sBh;
    C += (long)bz * sCb + (long)hz * sCh;
    if (R) R += (long)bz * sCb + (long)hz * sCh;

    int m0 = blockIdx.y * BM;
    int n0 = blockIdx.x * BN;
    int tid = threadIdx.x;
    int lane = tid & 31, warp = tid >> 5;
    int wm = warp & 3, wn = warp >> 2;    // 4 warps in M, 2 in N
    int qq = lane >> 2, rr = lane & 3;

    float acc[2][8][4];
#pragma unroll
    for (int mt = 0; mt < 2; mt++)
#pragma unroll
        for (int nt = 0; nt < 8; nt++)
#pragma unroll
            for (int rg = 0; rg < 4; rg++) acc[mt][nt][rg] = 0.f;

    // B vector path requires: 128 columns all readable, ldb multiple of 4
    const bool bvec = transB ? true : ((n0 + BN <= Nload) && ((ldb & 3) == 0));

    float4 ra[2];
    float4 rbv[2];
    float  rbs[8];

    // ---- staging: global -> registers ----
    auto loadAB = [&](int k0) {
#pragma unroll
        for (int i = 0; i < 2; i++) {
            int slot = tid + i * 256;   // 512 float4 slots: row=slot>>2, c4=slot&3
            ra[i] = *(const float4*)&A[(long)(m0 + (slot >> 2)) * lda + k0 + (slot & 3) * 4];
        }
        if (transB) {
#pragma unroll
            for (int i = 0; i < 2; i++) {
                int slot = tid + i * 256;
                rbv[i] = *(const float4*)&B[(long)(n0 + (slot >> 2)) * ldb + k0 + (slot & 3) * 4];
            }
        } else if (bvec) {
#pragma unroll
            for (int i = 0; i < 2; i++) {
                int slot = tid + i * 256; // row=slot>>5 (0..15), c4=slot&31
                rbv[i] = *(const float4*)&B[(long)(k0 + (slot >> 5)) * ldb + n0 + (slot & 31) * 4];
            }
        } else {
#pragma unroll
            for (int i = 0; i < 8; i++) {
                int slot = tid + i * 256; // row=slot>>7 (0..15), col=slot&127
                int n = n0 + (slot & 127);
                rbs[i] = (n < Nload) ? B[(long)(k0 + (slot >> 7)) * ldb + n] : 0.f;
            }
        }
    };

    // ---- staging: registers -> smem (with tf32 round) ----
    auto storeAB = [&]() {
#pragma unroll
        for (int i = 0; i < 2; i++) {
            int slot = tid + i * 256;
            uint32_t* p = &As[(slot >> 2) * LDA_S + (slot & 3) * 4];
            p[0] = f2tf32(ra[i].x); p[1] = f2tf32(ra[i].y);
            p[2] = f2tf32(ra[i].z); p[3] = f2tf32(ra[i].w);
        }
        if (transB) {
#pragma unroll
            for (int i = 0; i < 2; i++) {
                int slot = tid + i * 256;
                int n = slot >> 2, c = (slot & 3) * 4;
                Bs[(c + 0) * LDB_S + n] = f2tf32(rbv[i].x);
                Bs[(c + 1) * LDB_S + n] = f2tf32(rbv[i].y);
                Bs[(c + 2) * LDB_S + n] = f2tf32(rbv[i].z);
                Bs[(c + 3) * LDB_S + n] = f2tf32(rbv[i].w);
            }
        } else if (bvec) {
#pragma unroll
            for (int i = 0; i < 2; i++) {
                int slot = tid + i * 256;
                uint32_t* p = &Bs[(slot >> 5) * LDB_S + (slot & 31) * 4];
                p[0] = f2tf32(rbv[i].x); p[1] = f2tf32(rbv[i].y);
                p[2] = f2tf32(rbv[i].z); p[3] = f2tf32(rbv[i].w);
            }
        } else {
#pragma unroll
            for (int i = 0; i < 8; i++) {
                int slot = tid + i * 256;
                Bs[(slot >> 7) * LDB_S + (slot & 127)] = f2tf32(rbs[i]);
            }
        }
    };

    loadAB(0);
    storeAB();
    __syncthreads();

    for (int k0 = 0; k0 < K; k0 += BK) {
        bool more = (k0 + BK) < K;
        if (more) loadAB(k0 + BK);

#pragma unroll
        for (int ks = 0; ks < 2; ks++) {
            int kb = ks * 8;
            uint32_t af[2][4], bfr[8][2];
#pragma unroll
            for (int mt = 0; mt < 2; mt++) {
                const uint32_t* p = &As[(wm * 32 + mt * 16 + qq) * LDA_S + kb + rr];
                af[mt][0] = p[0];
                af[mt][1] = p[8 * LDA_S];
                af[mt][2] = p[4];
                af[mt][3] = p[8 * LDA_S + 4];
            }
#pragma unroll
            for (int nt = 0; nt < 8; nt++) {
                const uint32_t* p = &Bs[(kb + rr) * LDB_S + wn * 64 + nt * 8 + qq];
                bfr[nt][0] = p[0];
                bfr[nt][1] = p[4 * LDB_S];
            }
#pragma unroll
            for (int mt = 0; mt < 2; mt++)
#pragma unroll
                for (int nt = 0; nt < 8; nt++)
                    mma_tf32(acc[mt][nt], af[mt], bfr[nt]);
        }

        __syncthreads();
        if (more) { storeAB(); __syncthreads(); }
    }

    // ---- epilogue ----
#pragma unroll
    for (int mt = 0; mt < 2; mt++)
#pragma unroll
        for (int nt = 0; nt < 8; nt++)
#pragma unroll
            for (int rg = 0; rg < 4; rg++) {
                int row = m0 + wm * 32 + mt * 16 + qq + (rg >> 1) * 8;
                int col = n0 + wn * 64 + nt * 8 + rr * 2 + (rg & 1);
                if (row < M && col < N) {
                    float v = acc[mt][nt][rg] * alpha;
                    if (bias) v += bias[col];
                    if (R)    v += R[(long)row * ldc + col];
                    if (act)  v = 0.5f * v * (1.f + erff(v * 0.70710678118654752f));
                    C[(long)row * ldc + col] = v;
                }
            }
}

// ---------------- embedding ----------------
__global__ void embed_kernel(const int* __restrict__ idx, const float* __restrict__ tok,
                             const float* __restrict__ pos, float* __restrict__ x)
{
    long i = (long)blockIdx.x * 256 + threadIdx.x;
    if (i >= (long)NT * D_) return;
    int d = (int)(i % D_);
    long row = i / D_;
    int t = (int)(row % T_);
    x[i] = tok[(long)idx[row] * D_ + d] + pos[(long)t * D_ + d];
}

// ---------------- lm_w pad: [D, V] -> [D, VPAD] ----------------
__global__ void pad_lmw_kernel(const float* __restrict__ w, float* __restrict__ wp)
{
    long i = (long)blockIdx.x * 256 + threadIdx.x;
    if (i >= (long)D_ * VPAD) return;
    int col = (int)(i % VPAD);
    long row = i / VPAD;
    wp[i] = (col < V_) ? w[row * V_ + col] : 0.f;
}

// ---------------- layernorm (one block per row) ----------------
__global__ void layernorm_kernel(const float* __restrict__ x, const float* __restrict__ w,
                                 const float* __restrict__ b, float* __restrict__ y)
{
    int r = blockIdx.x;
    const float* xr = x + (long)r * D_;
    float* yr = y + (long)r * D_;
    __shared__ float s1[256], s2[256];
    int tid = threadIdx.x;
    float a = 0.f, sq = 0.f;
    for (int i = tid; i < D_; i += 256) { float v = xr[i]; a += v; sq += v * v; }
    s1[tid] = a; s2[tid] = sq; __syncthreads();
    for (int s = 128; s > 0; s >>= 1) {
        if (tid < s) { s1[tid] += s1[tid + s]; s2[tid] += s2[tid + s]; }
        __syncthreads();
    }
    float mu = s1[0] * (1.f / D_);
    float var = s2[0] * (1.f / D_) - mu * mu;
    float rstd = rsqrtf(var + 1e-5f);
    for (int i = tid; i < D_; i += 256)
        yr[i] = (xr[i] - mu) * rstd * w[i] + b[i];
}

// ---------------- causal softmax: single pass, row in registers ----------------
__global__ void softmax_causal_kernel(float* __restrict__ scores)
{
    int rrow = blockIdx.x;            // 0 .. B_*H_*T_-1
    int qpos = rrow & (T_ - 1);
    float4* row = (float4*)(scores + (long)rrow * T_);
    int tid = threadIdx.x;
    float4 v = row[tid];
    int b0 = tid * 4;

    float x0 = (b0     <= qpos) ? v.x : -1e30f;
    float x1 = (b0 + 1 <= qpos) ? v.y : -1e30f;
    float x2 = (b0 + 2 <= qpos) ? v.z : -1e30f;
    float x3 = (b0 + 3 <= qpos) ? v.w : -1e30f;

    float m = fmaxf(fmaxf(x0, x1), fmaxf(x2, x3));
#pragma unroll
    for (int o = 16; o; o >>= 1) m = fmaxf(m, __shfl_xor_sync(0xffffffffu, m, o));

    __shared__ float sm[8], ss[8];
    int w = tid >> 5, ln = tid & 31;
    if (ln == 0) sm[w] = m;
    __syncthreads();
    m = sm[0];
#pragma unroll
    for (int i = 1; i < 8; i++) m = fmaxf(m, sm[i]);

    float e0 = expf(x0 - m), e1 = expf(x1 - m), e2 = expf(x2 - m), e3 = expf(x3 - m);
    float s = e0 + e1 + e2 + e3;
#pragma unroll
    for (int o = 16; o; o >>= 1) s += __shfl_xor_sync(0xffffffffu, s, o);
    if (ln == 0) ss[w] = s;
    __syncthreads();
    s = ss[0];
#pragma unroll
    for (int i = 1; i < 8; i++) s += ss[i];
    float inv = 1.f / s;

    float4 o4;
    o4.x = e0 * inv; o4.y = e1 * inv; o4.z = e2 * inv; o4.w = e3 * inv;
    row[tid] = o4;
}

// ---------------- NLL: single-pass online logsumexp ----------------
__global__ void nll_kernel(const float* __restrict__ logits, const int* __restrict__ targets,
                           float* __restrict__ nll)
{
    int rrow = blockIdx.x;
    const float* row = logits + (long)rrow * V_;
    int tid = threadIdx.x;

    float m = -1e30f, s = 0.f;
    for (int i = tid; i < V_; i += 256) {
        float v = row[i];
        if (v > m) { s = s * expf(m - v); m = v; }
        s += expf(v - m);
    }
#pragma unroll
    for (int o = 16; o; o >>= 1) {
        float mo = __shfl_xor_sync(0xffffffffu, m, o);
        float so = __shfl_xor_sync(0xffffffffu, s, o);
        float mn = fmaxf(m, mo);
        s = s * expf(m - mn) + so * expf(mo - mn);
        m = mn;
    }
    __shared__ float smM[8], smS[8];
    if ((tid & 31) == 0) { smM[tid >> 5] = m; smS[tid >> 5] = s; }
    __syncthreads();
    if (tid == 0) {
        m = smM[0]; s = smS[0];
#pragma unroll
        for (int i = 1; i < 8; i++) {
            float mn = fmaxf(m, smM[i]);
            s = s * expf(m - mn) + smS[i] * expf(smM[i] - mn);
            m = mn;
        }
        float lse = m + logf(s);
        nll[rrow] = lse - row[targets[rrow]];
    }
}

// ---------------- NLL stage 2: mean ----------------
__global__ void loss_reduce_kernel(const float* __restrict__ nll, float* __restrict__ out)
{
    __shared__ float red[256];
    int tid = threadIdx.x;
    float a = 0.f;
    for (int i = tid; i < NT; i += 256) a += nll[i];
    red[tid] = a; __syncthreads();
    for (int s = 128; s > 0; s >>= 1) { if (tid < s) red[tid] += red[tid + s]; __syncthreads(); }
    if (tid == 0) out[0] = red[0] * (1.f / NT);
}

// ---------------- host-side helpers ----------------
static inline void launch_gemm(const float* A, const float* B, const float* bias, const float* R,
                               float* C, int M, int N, int Nload, int K, int lda, int ldb, int ldc,
                               long sAb, long sAh, long sBb, long sBh, long sCb, long sCh,
                               int batch, int batchH, float alpha, int transB, int act)
{
    dim3 grid((N + BN - 1) / BN, (M + BM - 1) / BM, batch);
    gemm_tf32_kernel<<<grid, 256>>>(A, B, bias, R, C, M, N, Nload, K, lda, ldb, ldc,
                                    sAb, sAh, sBb, sBh, sCb, sCh, batchH, alpha, transB, act);
}

extern "C" void kernel_launch(void* const* d_in, const int* in_sizes, int n_in,
                              void* d_out, int out_size)
{
    const float* tok_emb = (const float*)d_in[0];
    const float* pos_emb = (const float*)d_in[1];
    const float* ln1_w   = (const float*)d_in[2];
    const float* ln1_b   = (const float*)d_in[3];
    const float* ln2_w   = (const float*)d_in[4];
    const float* ln2_b   = (const float*)d_in[5];
    const float* wq      = (const float*)d_in[6];
    const float* wk      = (const float*)d_in[7];
    const float* wv      = (const float*)d_in[8];
    const float* wproj   = (const float*)d_in[9];
    const float* bproj   = (const float*)d_in[10];
    const float* w1      = (const float*)d_in[11];
    const float* b1      = (const float*)d_in[12];
    const float* w2      = (const float*)d_in[13];
    const float* b2      = (const float*)d_in[14];
    const float* lnf_w   = (const float*)d_in[15];
    const float* lnf_b   = (const float*)d_in[16];
    const float* lm_w    = (const float*)d_in[17];
    const float* lm_b    = (const float*)d_in[18];
    const int*   indexp  = (const int*)d_in[19];
    const int*   targets = (const int*)d_in[20];

    float* out = (float*)d_out;

    float *x, *h, *q, *k, *v, *att, *scores, *mlp, *nll, *lmw_pad;
    cudaGetSymbolAddress((void**)&x,       g_x);
    cudaGetSymbolAddress((void**)&h,       g_h);
    cudaGetSymbolAddress((void**)&q,       g_q);
    cudaGetSymbolAddress((void**)&k,       g_k);
    cudaGetSymbolAddress((void**)&v,       g_v);
    cudaGetSymbolAddress((void**)&att,     g_att);
    cudaGetSymbolAddress((void**)&scores,  g_scores);
    cudaGetSymbolAddress((void**)&mlp,     g_mlp);
    cudaGetSymbolAddress((void**)&nll,     g_nll);
    cudaGetSymbolAddress((void**)&lmw_pad, g_lmw_pad);

    // x = tok_emb[index] + pos_emb ; pad lm_w
    {
        long total = (long)NT * D_;
        embed_kernel<<<(int)((total + 255) / 256), 256>>>(indexp, tok_emb, pos_emb, x);
        long ptotal = (long)D_ * VPAD;
        pad_lmw_kernel<<<(int)((ptotal + 255) / 256), 256>>>(lm_w, lmw_pad);
    }

    const float scale = 1.0f / 8.0f;   // HD^-0.5

    for (int l = 0; l < L_; l++) {
        const float* wq_l = wq + (long)l * D_ * D_;
        const float* wk_l = wk + (long)l * D_ * D_;
        const float* wv_l = wv + (long)l * D_ * D_;
        const float* wp_l = wproj + (long)l * D_ * D_;
        const float* bp_l = bproj + (long)l * D_;
        const float* w1_l = w1 + (long)l * D_ * FF;
        const float* b1_l = b1 + (long)l * FF;
        const float* w2_l = w2 + (long)l * FF * D_;
        const float* b2_l = b2 + (long)l * D_;

        // h = LN1(x)
        layernorm_kernel<<<NT, 256>>>(x, ln1_w + (long)l * D_, ln1_b + (long)l * D_, h);

        // q,k,v = h @ W
        launch_gemm(h, wq_l, nullptr, nullptr, q, NT, D_, D_, D_, D_, D_, D_,
                    0, 0, 0, 0, 0, 0, 1, 1, 1.f, 0, 0);
        launch_gemm(h, wk_l, nullptr, nullptr, k, NT, D_, D_, D_, D_, D_, D_,
                    0, 0, 0, 0, 0, 0, 1, 1, 1.f, 0, 0);
        launch_gemm(h, wv_l, nullptr, nullptr, v, NT, D_, D_, D_, D_, D_, D_,
                    0, 0, 0, 0, 0, 0, 1, 1, 1.f, 0, 0);

        // scores = scale * Q @ K^T   (batched over b,h)
        launch_gemm(q, k, nullptr, nullptr, scores,
                    T_, T_, T_, HD_, D_, D_, T_,
                    (long)T_ * D_, HD_,
                    (long)T_ * D_, HD_,
                    (long)H_ * T_ * T_, (long)T_ * T_,
                    B_ * H_, H_, scale, 1, 0);

        // causal softmax
        softmax_causal_kernel<<<B_ * H_ * T_, 256>>>(scores);

        // att = wei @ V
        launch_gemm(scores, v, nullptr, nullptr, att,
                    T_, HD_, HD_, T_, T_, D_, D_,
                    (long)H_ * T_ * T_, (long)T_ * T_,
                    (long)T_ * D_, HD_,
                    (long)T_ * D_, HD_,
                    B_ * H_, H_, 1.f, 0, 0);

        // x = x + att @ wproj + bproj
        launch_gemm(att, wp_l, bp_l, x, x, NT, D_, D_, D_, D_, D_, D_,
                    0, 0, 0, 0, 0, 0, 1, 1, 1.f, 0, 0);

        // h = LN2(x)
        layernorm_kernel<<<NT, 256>>>(x, ln2_w + (long)l * D_, ln2_b + (long)l * D_, h);

        // mlp = gelu(h @ w1 + b1)
        launch_gemm(h, w1_l, b1_l, nullptr, mlp, NT, FF, FF, D_, D_, FF, FF,
                    0, 0, 0, 0, 0, 0, 1, 1, 1.f, 0, 1);

        // x = x + mlp @ w2 + b2
        launch_gemm(mlp, w2_l, b2_l, x, x, NT, D_, D_, FF, FF, D_, D_,
                    0, 0, 0, 0, 0, 0, 1, 1, 1.f, 0, 0);
    }

    // h = LNf(x)
    layernorm_kernel<<<NT, 256>>>(x, lnf_w, lnf_b, h);

    long logits_elems = (long)NT * V_;
    if ((long)out_size >= logits_elems) {
        // logits = h @ lm_w_pad + lm_b  (Nload=VPAD enables vector loads; stores bounded by V_)
        launch_gemm(h, lmw_pad, lm_b, nullptr, out, NT, V_, VPAD, D_, D_, VPAD, V_,
                    0, 0, 0, 0, 0, 0, 1, 1, 1.f, 0, 0);

        nll_kernel<<<NT, 256>>>(out, targets, nll);
        if ((long)out_size >= logits_elems + 1) {
            loss_reduce_kernel<<<1, 256>>>(nll, out + logits_elems);
        }
    }
}

// round 3
// speedup vs baseline: 3.1544x; 1.6262x over previous
#include <cuda_runtime.h>
#include <math.h>
#include <stdint.h>

// ---------------- problem constants ----------------
#define B_  4
#define T_  1024
#define D_  768
#define H_  12
#define HD_ 64
#define L_  6
#define V_  50257
#define VPAD 50304        // V padded to multiple of 128
#define NT  4096          // B_*T_
#define FF  3072          // 4*D_

// ---------------- scratch (static device globals; no allocation) ----------------
__device__ float g_x  [NT * D_];
__device__ float g_h  [NT * D_];
__device__ float g_q  [NT * D_];
__device__ float g_k  [NT * D_];
__device__ float g_v  [NT * D_];
__device__ float g_att[NT * D_];
__device__ float g_scores[48 * 1024 * 1024];   // B_*H_*T_*T_
__device__ float g_mlp[NT * FF];
__device__ float g_nll[NT];
__device__ float g_lmw_pad[(size_t)D_ * VPAD]; // padded lm_w for vector loads

// ---------------- tf32 helpers ----------------
__device__ __forceinline__ uint32_t f2tf32(float x) {
    uint32_t y;
    asm("cvt.rna.tf32.f32 %0, %1;" : "=r"(y) : "f"(x));
    return y;
}

__device__ __forceinline__ void mma_tf32(float* c, const uint32_t* a, const uint32_t* b) {
    asm volatile(
        "mma.sync.aligned.m16n8k8.row.col.f32.tf32.tf32.f32 "
        "{%0,%1,%2,%3},{%4,%5,%6,%7},{%8,%9},{%0,%1,%2,%3};"
        : "+f"(c[0]), "+f"(c[1]), "+f"(c[2]), "+f"(c[3])
        : "r"(a[0]), "r"(a[1]), "r"(a[2]), "r"(a[3]), "r"(b[0]), "r"(b[1]));
}

// ---------------- TF32 GEMM: C = act(alpha*A@B(^T) + bias + R) ----------------
// BM=128, BN_T in {128,64}, BK=16; 256 threads = 8 warps (4 in M x 2 in N).
// Double-buffered smem, one __syncthreads per k-iteration, 2 CTAs/SM.
#define BM 128
#define BK 16
#define LDA_S 20    // As[m][k] pad

template<int BN_T>
__global__ __launch_bounds__(256, 2)
void gemm_tf32_kernel(const float* __restrict__ A, const float* __restrict__ B,
                      const float* __restrict__ bias, const float* __restrict__ R,
                      float* __restrict__ C,
                      int M, int N, int Nload, int K, int lda, int ldb, int ldc,
                      long sAb, long sAh, long sBb, long sBh, long sCb, long sCh,
                      int batchH, float alpha, int transB, int act)
{
    constexpr int LDB_S = BN_T + 8;
    constexpr int NFR   = BN_T / 16;      // n-fragment tiles per warp (warp covers BN_T/2)
    constexpr int BL    = BN_T / 64;      // float4 B-load iterations per thread

    __shared__ uint32_t As[2][BM * LDA_S];
    __shared__ uint32_t Bs[2][BK * LDB_S];

    int z  = blockIdx.z;
    int bz = z / batchH, hz = z % batchH;
    A += (long)bz * sAb + (long)hz * sAh;
    B += (long)bz * sBb + (long)hz * sBh;
    C += (long)bz * sCb + (long)hz * sCh;
    if (R) R += (long)bz * sCb + (long)hz * sCh;

    int m0 = blockIdx.y * BM;
    int n0 = blockIdx.x * BN_T;
    int tid = threadIdx.x;
    int lane = tid & 31, warp = tid >> 5;
    int wm = warp & 3, wn = warp >> 2;    // 4 warps in M, 2 in N
    int qq = lane >> 2, rr = lane & 3;

    float acc[2][NFR][4];
#pragma unroll
    for (int mt = 0; mt < 2; mt++)
#pragma unroll
        for (int nt = 0; nt < NFR; nt++)
#pragma unroll
            for (int rg = 0; rg < 4; rg++) acc[mt][nt][rg] = 0.f;

    float4 ra[2];
    float4 rb[BL];

    // ---- staging: global -> registers (vector loads only; shapes guaranteed) ----
    auto loadAB = [&](int k0) {
#pragma unroll
        for (int i = 0; i < 2; i++) {
            int slot = tid + i * 256;   // 512 slots: row=slot>>2, c4=slot&3
            ra[i] = *(const float4*)&A[(long)(m0 + (slot >> 2)) * lda + k0 + (slot & 3) * 4];
        }
        if (transB) {
#pragma unroll
            for (int i = 0; i < BL; i++) {
                int slot = tid + i * 256;  // n=slot>>2, c4=slot&3
                rb[i] = *(const float4*)&B[(long)(n0 + (slot >> 2)) * ldb + k0 + (slot & 3) * 4];
            }
        } else {
#pragma unroll
            for (int i = 0; i < BL; i++) {
                int slot = tid + i * 256;  // row=slot/(BN_T/4), c4=slot%(BN_T/4)
                int row = slot / (BN_T / 4), c4 = slot % (BN_T / 4);
                rb[i] = *(const float4*)&B[(long)(k0 + row) * ldb + n0 + c4 * 4];
            }
        }
    };

    // ---- staging: registers -> smem (tf32 round) ----
    auto storeAB = [&](int buf) {
#pragma unroll
        for (int i = 0; i < 2; i++) {
            int slot = tid + i * 256;
            uint32_t* p = &As[buf][(slot >> 2) * LDA_S + (slot & 3) * 4];
            p[0] = f2tf32(ra[i].x); p[1] = f2tf32(ra[i].y);
            p[2] = f2tf32(ra[i].z); p[3] = f2tf32(ra[i].w);
        }
        if (transB) {
#pragma unroll
            for (int i = 0; i < BL; i++) {
                int slot = tid + i * 256;
                int n = slot >> 2, c = (slot & 3) * 4;
                Bs[buf][(c + 0) * LDB_S + n] = f2tf32(rb[i].x);
                Bs[buf][(c + 1) * LDB_S + n] = f2tf32(rb[i].y);
                Bs[buf][(c + 2) * LDB_S + n] = f2tf32(rb[i].z);
                Bs[buf][(c + 3) * LDB_S + n] = f2tf32(rb[i].w);
            }
        } else {
#pragma unroll
            for (int i = 0; i < BL; i++) {
                int slot = tid + i * 256;
                int row = slot / (BN_T / 4), c4 = slot % (BN_T / 4);
                uint32_t* p = &Bs[buf][row * LDB_S + c4 * 4];
                p[0] = f2tf32(rb[i].x); p[1] = f2tf32(rb[i].y);
                p[2] = f2tf32(rb[i].z); p[3] = f2tf32(rb[i].w);
            }
        }
    };

    loadAB(0);
    storeAB(0);
    __syncthreads();

    int buf = 0;
    for (int k0 = 0; k0 < K; k0 += BK) {
        bool more = (k0 + BK) < K;
        if (more) loadAB(k0 + BK);

#pragma unroll
        for (int ks = 0; ks < 2; ks++) {
            int kb = ks * 8;
            uint32_t af[2][4], bfr[NFR][2];
#pragma unroll
            for (int mt = 0; mt < 2; mt++) {
                const uint32_t* p = &As[buf][(wm * 32 + mt * 16 + qq) * LDA_S + kb + rr];
                af[mt][0] = p[0];
                af[mt][1] = p[8 * LDA_S];
                af[mt][2] = p[4];
                af[mt][3] = p[8 * LDA_S + 4];
            }
#pragma unroll
            for (int nt = 0; nt < NFR; nt++) {
                const uint32_t* p = &Bs[buf][(kb + rr) * LDB_S + wn * (BN_T / 2) + nt * 8 + qq];
                bfr[nt][0] = p[0];
                bfr[nt][1] = p[4 * LDB_S];
            }
#pragma unroll
            for (int mt = 0; mt < 2; mt++)
#pragma unroll
                for (int nt = 0; nt < NFR; nt++)
                    mma_tf32(acc[mt][nt], af[mt], bfr[nt]);
        }

        if (more) storeAB(buf ^ 1);
        __syncthreads();
        buf ^= 1;
    }

    // ---- epilogue ----
#pragma unroll
    for (int mt = 0; mt < 2; mt++)
#pragma unroll
        for (int nt = 0; nt < NFR; nt++)
#pragma unroll
            for (int rg = 0; rg < 4; rg++) {
                int row = m0 + wm * 32 + mt * 16 + qq + (rg >> 1) * 8;
                int col = n0 + wn * (BN_T / 2) + nt * 8 + rr * 2 + (rg & 1);
                if (row < M && col < N) {
                    float v = acc[mt][nt][rg] * alpha;
                    if (bias) v += bias[col];
                    if (R)    v += R[(long)row * ldc + col];
                    if (act)  v = 0.5f * v * (1.f + erff(v * 0.70710678118654752f));
                    C[(long)row * ldc + col] = v;
                }
            }
}

// ---------------- embedding ----------------
__global__ void embed_kernel(const int* __restrict__ idx, const float* __restrict__ tok,
                             const float* __restrict__ pos, float* __restrict__ x)
{
    long i = (long)blockIdx.x * 256 + threadIdx.x;
    if (i >= (long)NT * D_) return;
    int d = (int)(i % D_);
    long row = i / D_;
    int t = (int)(row % T_);
    x[i] = tok[(long)idx[row] * D_ + d] + pos[(long)t * D_ + d];
}

// ---------------- lm_w pad: [D, V] -> [D, VPAD] ----------------
__global__ void pad_lmw_kernel(const float* __restrict__ w, float* __restrict__ wp)
{
    long i = (long)blockIdx.x * 256 + threadIdx.x;
    if (i >= (long)D_ * VPAD) return;
    int col = (int)(i % VPAD);
    long row = i / VPAD;
    wp[i] = (col < V_) ? w[row * V_ + col] : 0.f;
}

// ---------------- layernorm (one block per row) ----------------
__global__ void layernorm_kernel(const float* __restrict__ x, const float* __restrict__ w,
                                 const float* __restrict__ b, float* __restrict__ y)
{
    int r = blockIdx.x;
    const float* xr = x + (long)r * D_;
    float* yr = y + (long)r * D_;
    __shared__ float s1[256], s2[256];
    int tid = threadIdx.x;
    float a = 0.f, sq = 0.f;
    for (int i = tid; i < D_; i += 256) { float v = xr[i]; a += v; sq += v * v; }
    s1[tid] = a; s2[tid] = sq; __syncthreads();
    for (int s = 128; s > 0; s >>= 1) {
        if (tid < s) { s1[tid] += s1[tid + s]; s2[tid] += s2[tid + s]; }
        __syncthreads();
    }
    float mu = s1[0] * (1.f / D_);
    float var = s2[0] * (1.f / D_) - mu * mu;
    float rstd = rsqrtf(var + 1e-5f);
    for (int i = tid; i < D_; i += 256)
        yr[i] = (xr[i] - mu) * rstd * w[i] + b[i];
}

// ---------------- causal softmax: single pass, row in registers ----------------
__global__ void softmax_causal_kernel(float* __restrict__ scores)
{
    int rrow = blockIdx.x;            // 0 .. B_*H_*T_-1
    int qpos = rrow & (T_ - 1);
    float4* row = (float4*)(scores + (long)rrow * T_);
    int tid = threadIdx.x;
    float4 v = row[tid];
    int b0 = tid * 4;

    float x0 = (b0     <= qpos) ? v.x : -1e30f;
    float x1 = (b0 + 1 <= qpos) ? v.y : -1e30f;
    float x2 = (b0 + 2 <= qpos) ? v.z : -1e30f;
    float x3 = (b0 + 3 <= qpos) ? v.w : -1e30f;

    float m = fmaxf(fmaxf(x0, x1), fmaxf(x2, x3));
#pragma unroll
    for (int o = 16; o; o >>= 1) m = fmaxf(m, __shfl_xor_sync(0xffffffffu, m, o));

    __shared__ float sm[8], ss[8];
    int w = tid >> 5, ln = tid & 31;
    if (ln == 0) sm[w] = m;
    __syncthreads();
    m = sm[0];
#pragma unroll
    for (int i = 1; i < 8; i++) m = fmaxf(m, sm[i]);

    float e0 = expf(x0 - m), e1 = expf(x1 - m), e2 = expf(x2 - m), e3 = expf(x3 - m);
    float s = e0 + e1 + e2 + e3;
#pragma unroll
    for (int o = 16; o; o >>= 1) s += __shfl_xor_sync(0xffffffffu, s, o);
    if (ln == 0) ss[w] = s;
    __syncthreads();
    s = ss[0];
#pragma unroll
    for (int i = 1; i < 8; i++) s += ss[i];
    float inv = 1.f / s;

    float4 o4;
    o4.x = e0 * inv; o4.y = e1 * inv; o4.z = e2 * inv; o4.w = e3 * inv;
    row[tid] = o4;
}

// ---------------- NLL: single-pass online logsumexp ----------------
__global__ void nll_kernel(const float* __restrict__ logits, const int* __restrict__ targets,
                           float* __restrict__ nll)
{
    int rrow = blockIdx.x;
    const float* row = logits + (long)rrow * V_;
    int tid = threadIdx.x;

    float m = -1e30f, s = 0.f;
    for (int i = tid; i < V_; i += 256) {
        float v = row[i];
        if (v > m) { s = s * expf(m - v); m = v; }
        s += expf(v - m);
    }
#pragma unroll
    for (int o = 16; o; o >>= 1) {
        float mo = __shfl_xor_sync(0xffffffffu, m, o);
        float so = __shfl_xor_sync(0xffffffffu, s, o);
        float mn = fmaxf(m, mo);
        s = s * expf(m - mn) + so * expf(mo - mn);
        m = mn;
    }
    __shared__ float smM[8], smS[8];
    if ((tid & 31) == 0) { smM[tid >> 5] = m; smS[tid >> 5] = s; }
    __syncthreads();
    if (tid == 0) {
        m = smM[0]; s = smS[0];
#pragma unroll
        for (int i = 1; i < 8; i++) {
            float mn = fmaxf(m, smM[i]);
            s = s * expf(m - mn) + smS[i] * expf(smM[i] - mn);
            m = mn;
        }
        float lse = m + logf(s);
        nll[rrow] = lse - row[targets[rrow]];
    }
}

// ---------------- NLL stage 2: mean ----------------
__global__ void loss_reduce_kernel(const float* __restrict__ nll, float* __restrict__ out)
{
    __shared__ float red[256];
    int tid = threadIdx.x;
    float a = 0.f;
    for (int i = tid; i < NT; i += 256) a += nll[i];
    red[tid] = a; __syncthreads();
    for (int s = 128; s > 0; s >>= 1) { if (tid < s) red[tid] += red[tid + s]; __syncthreads(); }
    if (tid == 0) out[0] = red[0] * (1.f / NT);
}

// ---------------- host-side helpers ----------------
static inline void launch_gemm(const float* A, const float* B, const float* bias, const float* R,
                               float* C, int M, int N, int Nload, int K, int lda, int ldb, int ldc,
                               long sAb, long sAh, long sBb, long sBh, long sCb, long sCh,
                               int batch, int batchH, float alpha, int transB, int act,
                               int bn = 128)
{
    if (bn == 128) {
        dim3 grid((Nload + 127) / 128, (M + BM - 1) / BM, batch);
        gemm_tf32_kernel<128><<<grid, 256>>>(A, B, bias, R, C, M, N, Nload, K, lda, ldb, ldc,
                                             sAb, sAh, sBb, sBh, sCb, sCh, batchH, alpha, transB, act);
    } else {
        dim3 grid((Nload + 63) / 64, (M + BM - 1) / BM, batch);
        gemm_tf32_kernel<64><<<grid, 256>>>(A, B, bias, R, C, M, N, Nload, K, lda, ldb, ldc,
                                            sAb, sAh, sBb, sBh, sCb, sCh, batchH, alpha, transB, act);
    }
}

extern "C" void kernel_launch(void* const* d_in, const int* in_sizes, int n_in,
                              void* d_out, int out_size)
{
    const float* tok_emb = (const float*)d_in[0];
    const float* pos_emb = (const float*)d_in[1];
    const float* ln1_w   = (const float*)d_in[2];
    const float* ln1_b   = (const float*)d_in[3];
    const float* ln2_w   = (const float*)d_in[4];
    const float* ln2_b   = (const float*)d_in[5];
    const float* wq      = (const float*)d_in[6];
    const float* wk      = (const float*)d_in[7];
    const float* wv      = (const float*)d_in[8];
    const float* wproj   = (const float*)d_in[9];
    const float* bproj   = (const float*)d_in[10];
    const float* w1      = (const float*)d_in[11];
    const float* b1      = (const float*)d_in[12];
    const float* w2      = (const float*)d_in[13];
    const float* b2      = (const float*)d_in[14];
    const float* lnf_w   = (const float*)d_in[15];
    const float* lnf_b   = (const float*)d_in[16];
    const float* lm_w    = (const float*)d_in[17];
    const float* lm_b    = (const float*)d_in[18];
    const int*   indexp  = (const int*)d_in[19];
    const int*   targets = (const int*)d_in[20];

    float* out = (float*)d_out;

    float *x, *h, *q, *k, *v, *att, *scores, *mlp, *nll, *lmw_pad;
    cudaGetSymbolAddress((void**)&x,       g_x);
    cudaGetSymbolAddress((void**)&h,       g_h);
    cudaGetSymbolAddress((void**)&q,       g_q);
    cudaGetSymbolAddress((void**)&k,       g_k);
    cudaGetSymbolAddress((void**)&v,       g_v);
    cudaGetSymbolAddress((void**)&att,     g_att);
    cudaGetSymbolAddress((void**)&scores,  g_scores);
    cudaGetSymbolAddress((void**)&mlp,     g_mlp);
    cudaGetSymbolAddress((void**)&nll,     g_nll);
    cudaGetSymbolAddress((void**)&lmw_pad, g_lmw_pad);

    // x = tok_emb[index] + pos_emb ; pad lm_w
    {
        long total = (long)NT * D_;
        embed_kernel<<<(int)((total + 255) / 256), 256>>>(indexp, tok_emb, pos_emb, x);
        long ptotal = (long)D_ * VPAD;
        pad_lmw_kernel<<<(int)((ptotal + 255) / 256), 256>>>(lm_w, lmw_pad);
    }

    const float scale = 1.0f / 8.0f;   // HD^-0.5

    for (int l = 0; l < L_; l++) {
        const float* wq_l = wq + (long)l * D_ * D_;
        const float* wk_l = wk + (long)l * D_ * D_;
        const float* wv_l = wv + (long)l * D_ * D_;
        const float* wp_l = wproj + (long)l * D_ * D_;
        const float* bp_l = bproj + (long)l * D_;
        const float* w1_l = w1 + (long)l * D_ * FF;
        const float* b1_l = b1 + (long)l * FF;
        const float* w2_l = w2 + (long)l * FF * D_;
        const float* b2_l = b2 + (long)l * D_;

        // h = LN1(x)
        layernorm_kernel<<<NT, 256>>>(x, ln1_w + (long)l * D_, ln1_b + (long)l * D_, h);

        // q,k,v = h @ W
        launch_gemm(h, wq_l, nullptr, nullptr, q, NT, D_, D_, D_, D_, D_, D_,
                    0, 0, 0, 0, 0, 0, 1, 1, 1.f, 0, 0);
        launch_gemm(h, wk_l, nullptr, nullptr, k, NT, D_, D_, D_, D_, D_, D_,
                    0, 0, 0, 0, 0, 0, 1, 1, 1.f, 0, 0);
        launch_gemm(h, wv_l, nullptr, nullptr, v, NT, D_, D_, D_, D_, D_, D_,
                    0, 0, 0, 0, 0, 0, 1, 1, 1.f, 0, 0);

        // scores = scale * Q @ K^T   (batched over b,h; transB)
        launch_gemm(q, k, nullptr, nullptr, scores,
                    T_, T_, T_, HD_, D_, D_, T_,
                    (long)T_ * D_, HD_,
                    (long)T_ * D_, HD_,
                    (long)H_ * T_ * T_, (long)T_ * T_,
                    B_ * H_, H_, scale, 1, 0);

        // causal softmax
        softmax_causal_kernel<<<B_ * H_ * T_, 256>>>(scores);

        // att = wei @ V   (N=64 -> BN=64 variant)
        launch_gemm(scores, v, nullptr, nullptr, att,
                    T_, HD_, HD_, T_, T_, D_, D_,
                    (long)H_ * T_ * T_, (long)T_ * T_,
                    (long)T_ * D_, HD_,
                    (long)T_ * D_, HD_,
                    B_ * H_, H_, 1.f, 0, 0, 64);

        // x = x + att @ wproj + bproj
        launch_gemm(att, wp_l, bp_l, x, x, NT, D_, D_, D_, D_, D_, D_,
                    0, 0, 0, 0, 0, 0, 1, 1, 1.f, 0, 0);

        // h = LN2(x)
        layernorm_kernel<<<NT, 256>>>(x, ln2_w + (long)l * D_, ln2_b + (long)l * D_, h);

        // mlp = gelu(h @ w1 + b1)
        launch_gemm(h, w1_l, b1_l, nullptr, mlp, NT, FF, FF, D_, D_, FF, FF,
                    0, 0, 0, 0, 0, 0, 1, 1, 1.f, 0, 1);

        // x = x + mlp @ w2 + b2
        launch_gemm(mlp, w2_l, b2_l, x, x, NT, D_, D_, FF, FF, D_, D_,
                    0, 0, 0, 0, 0, 0, 1, 1, 1.f, 0, 0);
    }

    // h = LNf(x)
    layernorm_kernel<<<NT, 256>>>(x, lnf_w, lnf_b, h);

    long logits_elems = (long)NT * V_;
    if ((long)out_size >= logits_elems) {
        // logits = h @ lm_w_pad + lm_b  (loads over VPAD, stores bounded by V_)
        launch_gemm(h, lmw_pad, lm_b, nullptr, out, NT, V_, VPAD, D_, D_, VPAD, V_,
                    0, 0, 0, 0, 0, 0, 1, 1, 1.f, 0, 0);

        nll_kernel<<<NT, 256>>>(out, targets, nll);
        if ((long)out_size >= logits_elems + 1) {
            loss_reduce_kernel<<<1, 256>>>(nll, out + logits_elems);
        }
    }
}

// round 6
// speedup vs baseline: 5.0168x; 1.5904x over previous
#include <cuda_runtime.h>
#include <cuda_fp16.h>
#include <math.h>
#include <stdint.h>

// ---------------- problem constants ----------------
#define B_  4
#define T_  1024
#define D_  768
#define H_  12
#define HD_ 64
#define L_  6
#define V_  50257
#define VPAD 50304
#define NT  4096
#define FF  3072

// ---------------- scratch ----------------
__device__ float  g_x  [NT * D_];
__device__ float  g_h  [NT * D_];
__device__ float  g_q  [NT * D_];
__device__ float  g_att[NT * D_];
__device__ float  g_scores[48 * 1024 * 1024];
__device__ float  g_mlp[NT * FF];
__device__ float  g_nll[NT];
__device__ __half g_k  [NT * D_];
__device__ __half g_vt [NT * D_];            // [B][H][HD][T]
__device__ __half g_wqT [L_ * D_ * D_];
__device__ __half g_wkT [L_ * D_ * D_];
__device__ __half g_wvT [L_ * D_ * D_];
__device__ __half g_wpT [L_ * D_ * D_];
__device__ __half g_w1T [L_ * FF * D_];      // [FF][D]
__device__ __half g_w2T [L_ * D_ * FF];      // [D][FF]
__device__ __half g_lmwT[(size_t)VPAD * D_];

// ---------------- helpers ----------------
__device__ __forceinline__ uint32_t smem_u32(const void* p) {
    uint32_t a;
    asm("{ .reg .u64 t; cvta.to.shared.u64 t, %1; cvt.u32.u64 %0, t; }" : "=r"(a) : "l"(p));
    return a;
}

__device__ __forceinline__ void ldm_x4(uint32_t* r, uint32_t addr) {
    asm volatile("ldmatrix.sync.aligned.m8n8.x4.shared.b16 {%0,%1,%2,%3}, [%4];"
        : "=r"(r[0]), "=r"(r[1]), "=r"(r[2]), "=r"(r[3]) : "r"(addr));
}

__device__ __forceinline__ void mma16816(float* c, const uint32_t* a, const uint32_t* b) {
    asm volatile(
        "mma.sync.aligned.m16n8k16.row.col.f32.f16.f16.f32 "
        "{%0,%1,%2,%3},{%4,%5,%6,%7},{%8,%9},{%0,%1,%2,%3};"
        : "+f"(c[0]), "+f"(c[1]), "+f"(c[2]), "+f"(c[3])
        : "r"(a[0]), "r"(a[1]), "r"(a[2]), "r"(a[3]), "r"(b[0]), "r"(b[1]));
}

__device__ __forceinline__ uint32_t pack_h2(float x, float y) {
    __half2 h = __floats2half2_rn(x, y);
    return *reinterpret_cast<uint32_t*>(&h);
}

// ---------------- fp16 mma.sync GEMM ----------------
// C[M,N] = act(alpha * A[M,K] @ Bt[N,K]^T + bias + R)
// A fp32 K-major; Bt half K-major; BK=32 double-buffered; rows padded to 80B.
#define BKC 32
#define RSTR 80     // smem row stride bytes (32 halves = 64B + 16B pad; 5 mod 8 -> conflict-free)

template<int BN, typename CT>
__global__ __launch_bounds__(256, 2)
void gemm_fp16_kernel(const float* __restrict__ A, const __half* __restrict__ Bt,
                      const float* __restrict__ bias, const float* __restrict__ R,
                      CT* __restrict__ C,
                      int M, int Nstore, int K, int lda, int ldb, int ldc,
                      long sAb, long sAh, long sBb, long sBh, long sCb, long sCh,
                      int batchH, float alpha, int act, int transC)
{
    extern __shared__ __align__(16) char dynsmem[];
    constexpr int ABUF  = 128 * RSTR;
    constexpr int BBUF  = BN * RSTR;
    constexpr int BUFSZ = ABUF + BBUF;
    constexpr int NFR   = BN / 16;       // n8 tiles per warp (warp covers BN/2 cols)
    constexpr int NBL   = BN / 64;       // B uint4 loads per thread
    constexpr int BNP   = BN + 1;

    uint32_t sbase = smem_u32(dynsmem);
    int tid = threadIdx.x;
    int lane = tid & 31, warp = tid >> 5;
    int wm = warp & 3, wn = warp >> 2;

    int z  = blockIdx.z;
    int bz = z / batchH, hz = z % batchH;
    A  += (long)bz * sAb + (long)hz * sAh;
    Bt += (long)bz * sBb + (long)hz * sBh;
    C  += (long)bz * sCb + (long)hz * sCh;
    if (R) R += (long)bz * sCb + (long)hz * sCh;

    int m0 = blockIdx.y * 128;
    int n0 = blockIdx.x * BN;

    float acc[2][NFR][4];
#pragma unroll
    for (int mt = 0; mt < 2; mt++)
#pragma unroll
        for (int nt = 0; nt < NFR; nt++)
#pragma unroll
            for (int rg = 0; rg < 4; rg++) acc[mt][nt][rg] = 0.f;

    float4 ra[4];
    uint4  rbv[NBL];

    auto ldreg = [&](int c) {
        int k0 = c * BKC;
#pragma unroll
        for (int i = 0; i < 4; i++) {
            int s = tid + i * 256;                 // row = s>>3, float4 chunk = s&7
            ra[i] = *(const float4*)&A[(long)(m0 + (s >> 3)) * lda + k0 + (s & 7) * 4];
        }
#pragma unroll
        for (int i = 0; i < NBL; i++) {
            int s = tid + i * 256;                 // row = s>>2, 8-half chunk = s&3
            rbv[i] = *(const uint4*)&Bt[(long)(n0 + (s >> 2)) * ldb + k0 + (s & 3) * 8];
        }
    };

    auto sts = [&](int buf) {
        uint32_t ab = sbase + buf * BUFSZ;
#pragma unroll
        for (int i = 0; i < 4; i++) {
            int s = tid + i * 256;
            uint32_t off = (uint32_t)((s >> 3) * RSTR + (s & 7) * 8);
            uint32_t lo = pack_h2(ra[i].x, ra[i].y);
            uint32_t hi = pack_h2(ra[i].z, ra[i].w);
            asm volatile("st.shared.v2.b32 [%0], {%1, %2};" :: "r"(ab + off), "r"(lo), "r"(hi) : "memory");
        }
        uint32_t bb = ab + ABUF;
#pragma unroll
        for (int i = 0; i < NBL; i++) {
            int s = tid + i * 256;
            uint32_t off = (uint32_t)((s >> 2) * RSTR + (s & 3) * 16);
            asm volatile("st.shared.v4.b32 [%0], {%1, %2, %3, %4};" ::
                "r"(bb + off), "r"(rbv[i].x), "r"(rbv[i].y), "r"(rbv[i].z), "r"(rbv[i].w) : "memory");
        }
    };

    int nchunks = K / BKC;
    ldreg(0);
    sts(0);
    __syncthreads();

    int buf = 0;
    for (int c = 0; c < nchunks; c++) {
        bool more = (c + 1) < nchunks;
        if (more) ldreg(c + 1);

        uint32_t abuf = sbase + buf * BUFSZ;
        uint32_t bbuf = abuf + ABUF;
#pragma unroll
        for (int ks = 0; ks < 2; ks++) {
            uint32_t af[2][4], bf[NFR][2];
#pragma unroll
            for (int mt = 0; mt < 2; mt++) {
                uint32_t addr = abuf + (uint32_t)((wm * 32 + mt * 16 + (lane & 15)) * RSTR)
                              + ks * 32 + ((lane >> 4) << 4);
                ldm_x4(af[mt], addr);
            }
#pragma unroll
            for (int p = 0; p < NFR / 2; p++) {
                uint32_t rr4[4];
                uint32_t addr = bbuf + (uint32_t)((wn * (BN / 2) + p * 16 + (lane & 7) + ((lane >> 4) << 3)) * RSTR)
                              + ks * 32 + (((lane >> 3) & 1) << 4);
                ldm_x4(rr4, addr);
                bf[2 * p][0] = rr4[0]; bf[2 * p][1] = rr4[1];
                bf[2 * p + 1][0] = rr4[2]; bf[2 * p + 1][1] = rr4[3];
            }
#pragma unroll
            for (int mt = 0; mt < 2; mt++)
#pragma unroll
                for (int nt = 0; nt < NFR; nt++)
                    mma16816(acc[mt][nt], af[mt], bf[nt]);
        }

        if (more) sts(buf ^ 1);
        __syncthreads();
        buf ^= 1;
    }

    // ---- epilogue: fragments -> smem (coalesce) -> global ----
    {
        float* ep = (float*)dynsmem;
        int qq = lane >> 2, rr = lane & 3;
#pragma unroll
        for (int mt = 0; mt < 2; mt++)
#pragma unroll
            for (int nt = 0; nt < NFR; nt++)
#pragma unroll
                for (int rg = 0; rg < 4; rg++) {
                    int row = wm * 32 + mt * 16 + qq + (rg >> 1) * 8;
                    int col = wn * (BN / 2) + nt * 8 + rr * 2 + (rg & 1);
                    int gn = n0 + col;
                    float v = acc[mt][nt][rg] * alpha;
                    if (bias && gn < Nstore) v += bias[gn];
                    if (act) v = 0.5f * v * (1.f + erff(v * 0.70710678118654752f));
                    ep[row * BNP + col] = v;
                }
        __syncthreads();

        if (!transC) {
            for (int idx = tid; idx < 128 * BN; idx += 256) {
                int r2 = idx / BN, c2 = idx % BN;
                int gn = n0 + c2;
                if (gn < Nstore) {
                    long gaddr = (long)(m0 + r2) * ldc + gn;
                    float v = ep[r2 * BNP + c2];
                    if (R) v += R[gaddr];
                    C[gaddr] = (CT)v;
                }
            }
        } else {
            // C layout: [b][h][hd][t]; m=(b,t), n=(h,hd)
            for (int idx = tid; idx < 128 * BN; idx += 256) {
                int r2 = idx & 127, c2 = idx >> 7;
                int gm = m0 + r2, gn = n0 + c2;
                int b = gm >> 10, t = gm & 1023;
                int hh = gn >> 6, hd = gn & 63;
                C[(((long)b * H_ + hh) * HD_ + hd) * T_ + t] = (CT)ep[r2 * BNP + c2];
            }
        }
    }
}

// ---------------- weight transpose+convert: in[K,N] fp32 -> out[N,K] half ----------------
__global__ void transpose_kernel(const float* __restrict__ in, __half* __restrict__ out,
                                 int Kd, int Nd, int Nout, long sIn, long sOut)
{
    __shared__ float t[32][33];
    int zz = blockIdx.z;
    in  += (long)zz * sIn;
    out += (long)zz * sOut;
    int n = blockIdx.x * 32 + threadIdx.x;
#pragma unroll
    for (int j = 0; j < 4; j++) {
        int k = blockIdx.y * 32 + threadIdx.y + j * 8;
        t[threadIdx.y + j * 8][threadIdx.x] = (n < Nd && k < Kd) ? in[(long)k * Nd + n] : 0.f;
    }
    __syncthreads();
#pragma unroll
    for (int j = 0; j < 4; j++) {
        int n2 = blockIdx.x * 32 + threadIdx.y + j * 8;
        int k2 = blockIdx.y * 32 + threadIdx.x;
        if (n2 < Nout && k2 < Kd) out[(long)n2 * Kd + k2] = __float2half(t[threadIdx.x][threadIdx.y + j * 8]);
    }
}

// ---------------- embedding ----------------
__global__ void embed_kernel(const int* __restrict__ idx, const float* __restrict__ tok,
                             const float* __restrict__ pos, float* __restrict__ x)
{
    long i = (long)blockIdx.x * 256 + threadIdx.x;
    if (i >= (long)NT * D_) return;
    int d = (int)(i % D_);
    long row = i / D_;
    int t = (int)(row % T_);
    x[i] = tok[(long)idx[row] * D_ + d] + pos[(long)t * D_ + d];
}

// ---------------- layernorm ----------------
__global__ void layernorm_kernel(const float* __restrict__ x, const float* __restrict__ w,
                                 const float* __restrict__ b, float* __restrict__ y)
{
    int r = blockIdx.x;
    const float* xr = x + (long)r * D_;
    float* yr = y + (long)r * D_;
    __shared__ float s1[256], s2[256];
    int tid = threadIdx.x;
    float a = 0.f, sq = 0.f;
    for (int i = tid; i < D_; i += 256) { float v = xr[i]; a += v; sq += v * v; }
    s1[tid] = a; s2[tid] = sq; __syncthreads();
    for (int s = 128; s > 0; s >>= 1) {
        if (tid < s) { s1[tid] += s1[tid + s]; s2[tid] += s2[tid + s]; }
        __syncthreads();
    }
    float mu = s1[0] * (1.f / D_);
    float var = s2[0] * (1.f / D_) - mu * mu;
    float rstd = rsqrtf(var + 1e-5f);
    for (int i = tid; i < D_; i += 256)
        yr[i] = (xr[i] - mu) * rstd * w[i] + b[i];
}

// ---------------- causal softmax ----------------
__global__ void softmax_causal_kernel(float* __restrict__ scores)
{
    int rrow = blockIdx.x;
    int qpos = rrow & (T_ - 1);
    float4* row = (float4*)(scores + (long)rrow * T_);
    int tid = threadIdx.x;
    float4 v = row[tid];
    int b0 = tid * 4;

    float x0 = (b0     <= qpos) ? v.x : -1e30f;
    float x1 = (b0 + 1 <= qpos) ? v.y : -1e30f;
    float x2 = (b0 + 2 <= qpos) ? v.z : -1e30f;
    float x3 = (b0 + 3 <= qpos) ? v.w : -1e30f;

    float m = fmaxf(fmaxf(x0, x1), fmaxf(x2, x3));
#pragma unroll
    for (int o = 16; o; o >>= 1) m = fmaxf(m, __shfl_xor_sync(0xffffffffu, m, o));

    __shared__ float sm[8], ss[8];
    int w = tid >> 5, ln = tid & 31;
    if (ln == 0) sm[w] = m;
    __syncthreads();
    m = sm[0];
#pragma unroll
    for (int i = 1; i < 8; i++) m = fmaxf(m, sm[i]);

    float e0 = expf(x0 - m), e1 = expf(x1 - m), e2 = expf(x2 - m), e3 = expf(x3 - m);
    float s = e0 + e1 + e2 + e3;
#pragma unroll
    for (int o = 16; o; o >>= 1) s += __shfl_xor_sync(0xffffffffu, s, o);
    if (ln == 0) ss[w] = s;
    __syncthreads();
    s = ss[0];
#pragma unroll
    for (int i = 1; i < 8; i++) s += ss[i];
    float inv = 1.f / s;

    float4 o4;
    o4.x = e0 * inv; o4.y = e1 * inv; o4.z = e2 * inv; o4.w = e3 * inv;
    row[tid] = o4;
}

// ---------------- NLL ----------------
__global__ void nll_kernel(const float* __restrict__ logits, const int* __restrict__ targets,
                           float* __restrict__ nll)
{
    int rrow = blockIdx.x;
    const float* row = logits + (long)rrow * V_;
    int tid = threadIdx.x;

    float m = -1e30f, s = 0.f;
    for (int i = tid; i < V_; i += 256) {
        float v = row[i];
        if (v > m) { s = s * expf(m - v); m = v; }
        s += expf(v - m);
    }
#pragma unroll
    for (int o = 16; o; o >>= 1) {
        float mo = __shfl_xor_sync(0xffffffffu, m, o);
        float so = __shfl_xor_sync(0xffffffffu, s, o);
        float mn = fmaxf(m, mo);
        s = s * expf(m - mn) + so * expf(mo - mn);
        m = mn;
    }
    __shared__ float smM[8], smS[8];
    if ((tid & 31) == 0) { smM[tid >> 5] = m; smS[tid >> 5] = s; }
    __syncthreads();
    if (tid == 0) {
        m = smM[0]; s = smS[0];
#pragma unroll
        for (int i = 1; i < 8; i++) {
            float mn = fmaxf(m, smM[i]);
            s = s * expf(m - mn) + smS[i] * expf(smM[i] - mn);
            m = mn;
        }
        float lse = m + logf(s);
        nll[rrow] = lse - row[targets[rrow]];
    }
}

__global__ void loss_reduce_kernel(const float* __restrict__ nll, float* __restrict__ out)
{
    __shared__ float red[256];
    int tid = threadIdx.x;
    float a = 0.f;
    for (int i = tid; i < NT; i += 256) a += nll[i];
    red[tid] = a; __syncthreads();
    for (int s = 128; s > 0; s >>= 1) { if (tid < s) red[tid] += red[tid + s]; __syncthreads(); }
    if (tid == 0) out[0] = red[0] * (1.f / NT);
}

// ---------------- host ----------------
#define SMEM128 66048   // max(2*(128+128)*80 = 40960, 128*129*4 = 66048)
#define SMEM64  33280   // max(2*(128+64)*80  = 30720, 128*65*4  = 33280)

extern "C" void kernel_launch(void* const* d_in, const int* in_sizes, int n_in,
                              void* d_out, int out_size)
{
    const float* tok_emb = (const float*)d_in[0];
    const float* pos_emb = (const float*)d_in[1];
    const float* ln1_w   = (const float*)d_in[2];
    const float* ln1_b   = (const float*)d_in[3];
    const float* ln2_w   = (const float*)d_in[4];
    const float* ln2_b   = (const float*)d_in[5];
    const float* wq      = (const float*)d_in[6];
    const float* wk      = (const float*)d_in[7];
    const float* wv      = (const float*)d_in[8];
    const float* wproj   = (const float*)d_in[9];
    const float* bproj   = (const float*)d_in[10];
    const float* w1      = (const float*)d_in[11];
    const float* b1      = (const float*)d_in[12];
    const float* w2      = (const float*)d_in[13];
    const float* b2      = (const float*)d_in[14];
    const float* lnf_w   = (const float*)d_in[15];
    const float* lnf_b   = (const float*)d_in[16];
    const float* lm_w    = (const float*)d_in[17];
    const float* lm_b    = (const float*)d_in[18];
    const int*   indexp  = (const int*)d_in[19];
    const int*   targets = (const int*)d_in[20];

    float* out = (float*)d_out;

    cudaFuncSetAttribute(gemm_fp16_kernel<128, float>,  cudaFuncAttributeMaxDynamicSharedMemorySize, SMEM128);
    cudaFuncSetAttribute(gemm_fp16_kernel<128, __half>, cudaFuncAttributeMaxDynamicSharedMemorySize, SMEM128);
    cudaFuncSetAttribute(gemm_fp16_kernel<64,  float>,  cudaFuncAttributeMaxDynamicSharedMemorySize, SMEM64);

    float *x, *h, *q, *att, *scores, *mlp, *nll;
    __half *kh, *vt, *wqT, *wkT, *wvT, *wpT, *w1T, *w2T, *lmwT;
    cudaGetSymbolAddress((void**)&x,      g_x);
    cudaGetSymbolAddress((void**)&h,      g_h);
    cudaGetSymbolAddress((void**)&q,      g_q);
    cudaGetSymbolAddress((void**)&att,    g_att);
    cudaGetSymbolAddress((void**)&scores, g_scores);
    cudaGetSymbolAddress((void**)&mlp,    g_mlp);
    cudaGetSymbolAddress((void**)&nll,    g_nll);
    cudaGetSymbolAddress((void**)&kh,     g_k);
    cudaGetSymbolAddress((void**)&vt,     g_vt);
    cudaGetSymbolAddress((void**)&wqT,    g_wqT);
    cudaGetSymbolAddress((void**)&wkT,    g_wkT);
    cudaGetSymbolAddress((void**)&wvT,    g_wvT);
    cudaGetSymbolAddress((void**)&wpT,    g_wpT);
    cudaGetSymbolAddress((void**)&w1T,    g_w1T);
    cudaGetSymbolAddress((void**)&w2T,    g_w2T);
    cudaGetSymbolAddress((void**)&lmwT,   g_lmwT);

    // embeddings + weight transposes (fp32 -> half, K-major)
    {
        long total = (long)NT * D_;
        embed_kernel<<<(int)((total + 255) / 256), 256>>>(indexp, tok_emb, pos_emb, x);

        dim3 tb(32, 8);
        dim3 gdd(D_ / 32, D_ / 32, L_);
        transpose_kernel<<<gdd, tb>>>(wq,    wqT, D_, D_, D_, (long)D_ * D_, (long)D_ * D_);
        transpose_kernel<<<gdd, tb>>>(wk,    wkT, D_, D_, D_, (long)D_ * D_, (long)D_ * D_);
        transpose_kernel<<<gdd, tb>>>(wv,    wvT, D_, D_, D_, (long)D_ * D_, (long)D_ * D_);
        transpose_kernel<<<gdd, tb>>>(wproj, wpT, D_, D_, D_, (long)D_ * D_, (long)D_ * D_);
        dim3 g1(FF / 32, D_ / 32, L_);
        transpose_kernel<<<g1, tb>>>(w1, w1T, D_, FF, FF, (long)D_ * FF, (long)FF * D_);
        dim3 g2(D_ / 32, FF / 32, L_);
        transpose_kernel<<<g2, tb>>>(w2, w2T, FF, D_, D_, (long)FF * D_, (long)D_ * FF);
        dim3 g3(VPAD / 32, D_ / 32, 1);
        transpose_kernel<<<g3, tb>>>(lm_w, lmwT, D_, V_, VPAD, 0, 0);
    }

    const float scale = 1.0f / 8.0f;

    for (int l = 0; l < L_; l++) {
        const __half* wqT_l = wqT + (long)l * D_ * D_;
        const __half* wkT_l = wkT + (long)l * D_ * D_;
        const __half* wvT_l = wvT + (long)l * D_ * D_;
        const __half* wpT_l = wpT + (long)l * D_ * D_;
        const float*  bp_l  = bproj + (long)l * D_;
        const __half* w1T_l = w1T + (long)l * FF * D_;
        const float*  b1_l  = b1 + (long)l * FF;
        const __half* w2T_l = w2T + (long)l * D_ * FF;
        const float*  b2_l  = b2 + (long)l * D_;

        layernorm_kernel<<<NT, 256>>>(x, ln1_w + (long)l * D_, ln1_b + (long)l * D_, h);

        // q (fp32), k (half), vT (half, transposed layout)
        gemm_fp16_kernel<128, float><<<dim3(D_ / 128, NT / 128, 1), 256, SMEM128>>>(
            h, wqT_l, nullptr, nullptr, q, NT, D_, D_, D_, D_, D_,
            0, 0, 0, 0, 0, 0, 1, 1.f, 0, 0);
        gemm_fp16_kernel<128, __half><<<dim3(D_ / 128, NT / 128, 1), 256, SMEM128>>>(
            h, wkT_l, nullptr, nullptr, kh, NT, D_, D_, D_, D_, D_,
            0, 0, 0, 0, 0, 0, 1, 1.f, 0, 0);
        gemm_fp16_kernel<128, __half><<<dim3(D_ / 128, NT / 128, 1), 256, SMEM128>>>(
            h, wvT_l, nullptr, nullptr, vt, NT, D_, D_, D_, D_, D_,
            0, 0, 0, 0, 0, 0, 1, 1.f, 0, 1);

        // scores = scale * Q @ K^T  (batch 48)
        gemm_fp16_kernel<128, float><<<dim3(T_ / 128, T_ / 128, B_ * H_), 256, SMEM128>>>(
            q, kh, nullptr, nullptr, scores, T_, T_, HD_, D_, D_, T_,
            (long)T_ * D_, 64, (long)T_ * D_, 64,
            (long)H_ * T_ * T_, (long)T_ * T_, H_, scale, 0, 0);

        softmax_causal_kernel<<<B_ * H_ * T_, 256>>>(scores);

        // att = P @ V  (B = vT, K-major over t; N=64)
        gemm_fp16_kernel<64, float><<<dim3(1, T_ / 128, B_ * H_), 256, SMEM64>>>(
            scores, vt, nullptr, nullptr, att, T_, HD_, T_, T_, T_, D_,
            (long)H_ * T_ * T_, (long)T_ * T_,
            (long)H_ * HD_ * T_, (long)HD_ * T_,
            (long)T_ * D_, 64, H_, 1.f, 0, 0);

        // x += att @ wproj + bproj
        gemm_fp16_kernel<128, float><<<dim3(D_ / 128, NT / 128, 1), 256, SMEM128>>>(
            att, wpT_l, bp_l, x, x, NT, D_, D_, D_, D_, D_,
            0, 0, 0, 0, 0, 0, 1, 1.f, 0, 0);

        layernorm_kernel<<<NT, 256>>>(x, ln2_w + (long)l * D_, ln2_b + (long)l * D_, h);

        // mlp = gelu(h @ w1 + b1)
        gemm_fp16_kernel<128, float><<<dim3(FF / 128, NT / 128, 1), 256, SMEM128>>>(
            h, w1T_l, b1_l, nullptr, mlp, NT, FF, D_, D_, D_, FF,
            0, 0, 0, 0, 0, 0, 1, 1.f, 1, 0);

        // x += mlp @ w2 + b2
        gemm_fp16_kernel<128, float><<<dim3(D_ / 128, NT / 128, 1), 256, SMEM128>>>(
            mlp, w2T_l, b2_l, x, x, NT, D_, FF, FF, FF, D_,
            0, 0, 0, 0, 0, 0, 1, 1.f, 0, 0);
    }

    layernorm_kernel<<<NT, 256>>>(x, lnf_w, lnf_b, h);

    long logits_elems = (long)NT * V_;
    if ((long)out_size >= logits_elems) {
        gemm_fp16_kernel<128, float><<<dim3(VPAD / 128, NT / 128, 1), 256, SMEM128>>>(
            h, lmwT, lm_b, nullptr, out, NT, V_, D_, D_, D_, V_,
            0, 0, 0, 0, 0, 0, 1, 1.f, 0, 0);

        nll_kernel<<<NT, 256>>>(out, targets, nll);
        if ((long)out_size >= logits_elems + 1) {
            loss_reduce_kernel<<<1, 256>>>(nll, out + logits_elems);
        }
    }
}

// round 8
// speedup vs baseline: 6.2647x; 1.2488x over previous
#include <cuda_runtime.h>
#include <cuda_fp16.h>
#include <math.h>
#include <stdint.h>

// ---------------- problem constants ----------------
#define B_  4
#define T_  1024
#define D_  768
#define H_  12
#define HD_ 64
#define L_  6
#define V_  50257
#define VPAD 50304
#define NT  4096
#define FF  3072

// ---------------- scratch ----------------
__device__ float  g_x  [NT * D_];
__device__ float  g_scores[48 * 1024 * 1024];
__device__ float  g_nll[NT];
__device__ __half g_h  [NT * D_];
__device__ __half g_q  [NT * D_];
__device__ __half g_k  [NT * D_];
__device__ __half g_vt [NT * D_];            // [B][H][HD][T]
__device__ __half g_att[NT * D_];
__device__ __half g_p  [48 * 1024 * 1024];   // softmax probs (half)
__device__ __half g_mlp[NT * FF];
__device__ __half g_wqT [L_ * D_ * D_];
__device__ __half g_wkT [L_ * D_ * D_];
__device__ __half g_wvT [L_ * D_ * D_];
__device__ __half g_wpT [L_ * D_ * D_];
__device__ __half g_w1T [L_ * FF * D_];      // [FF][D]
__device__ __half g_w2T [L_ * D_ * FF];      // [D][FF]
__device__ __half g_lmwT[(size_t)VPAD * D_];

// ---------------- helpers ----------------
__device__ __forceinline__ uint32_t smem_u32(const void* p) {
    uint32_t a;
    asm("{ .reg .u64 t; cvta.to.shared.u64 t, %1; cvt.u32.u64 %0, t; }" : "=r"(a) : "l"(p));
    return a;
}
__device__ __forceinline__ void ldm_x4(uint32_t* r, uint32_t addr) {
    asm volatile("ldmatrix.sync.aligned.m8n8.x4.shared.b16 {%0,%1,%2,%3}, [%4];"
        : "=r"(r[0]), "=r"(r[1]), "=r"(r[2]), "=r"(r[3]) : "r"(addr));
}
__device__ __forceinline__ void mma16816(float* c, const uint32_t* a, const uint32_t* b) {
    asm volatile(
        "mma.sync.aligned.m16n8k16.row.col.f32.f16.f16.f32 "
        "{%0,%1,%2,%3},{%4,%5,%6,%7},{%8,%9},{%0,%1,%2,%3};"
        : "+f"(c[0]), "+f"(c[1]), "+f"(c[2]), "+f"(c[3])
        : "r"(a[0]), "r"(a[1]), "r"(a[2]), "r"(a[3]), "r"(b[0]), "r"(b[1]));
}
#define CP_ASYNC16(dst, src) \
    asm volatile("cp.async.cg.shared.global [%0], [%1], 16;" :: "r"(dst), "l"(src) : "memory")
#define CP_COMMIT() asm volatile("cp.async.commit_group;" ::: "memory")
#define CP_WAIT(n)  asm volatile("cp.async.wait_group %0;" :: "n"(n) : "memory")

// ---------------- fp16 mma.sync GEMM with cp.async 4-stage pipeline ----------------
// C[M,N] = act(alpha * A[M,K] @ Bt[N,K]^T + bias + R); A, Bt half K-major.
#define BKC 32
#define RSTR 80       // smem row stride bytes (64B data + 16B pad; conflict-free)
#define NSTAGE 4

template<int BN, typename CT>
__global__ __launch_bounds__(256, 2)
void gemm_h_kernel(const __half* __restrict__ A, const __half* __restrict__ Bt,
                   const float* __restrict__ bias, const float* __restrict__ R,
                   CT* __restrict__ C,
                   int M, int Nstore, int K, int lda, int ldb, int ldc,
                   long sAb, long sAh, long sBb, long sBh, long sCb, long sCh,
                   int batchH, float alpha, int act, int transC)
{
    extern __shared__ __align__(16) char dynsmem[];
    constexpr int ABUF  = 128 * RSTR;
    constexpr int BBUF  = BN * RSTR;
    constexpr int BUFSZ = ABUF + BBUF;
    constexpr int NFR   = BN / 16;
    constexpr int NBL   = BN / 64;     // B 16B transfers per thread
    constexpr int BNP   = BN + 1;

    uint32_t sbase = smem_u32(dynsmem);
    int tid = threadIdx.x;
    int lane = tid & 31, warp = tid >> 5;
    int wm = warp & 3, wn = warp >> 2;

    int z  = blockIdx.z;
    int bz = z / batchH, hz = z % batchH;
    A  += (long)bz * sAb + (long)hz * sAh;
    Bt += (long)bz * sBb + (long)hz * sBh;
    C  += (long)bz * sCb + (long)hz * sCh;
    if (R) R += (long)bz * sCb + (long)hz * sCh;

    int m0 = blockIdx.y * 128;
    int n0 = blockIdx.x * BN;

    float acc[2][NFR][4];
#pragma unroll
    for (int mt = 0; mt < 2; mt++)
#pragma unroll
        for (int nt = 0; nt < NFR; nt++)
#pragma unroll
            for (int rg = 0; rg < 4; rg++) acc[mt][nt][rg] = 0.f;

    int nchunks = K / BKC;

    auto issue = [&](int c) {
        int k0 = c * BKC;
        uint32_t ab = sbase + (c % NSTAGE) * BUFSZ;
#pragma unroll
        for (int i = 0; i < 2; i++) {
            int s = tid + i * 256;                     // row = s>>2, 16B chunk = s&3
            uint32_t dst = ab + (uint32_t)((s >> 2) * RSTR + (s & 3) * 16);
            const __half* src = &A[(long)(m0 + (s >> 2)) * lda + k0 + (s & 3) * 8];
            CP_ASYNC16(dst, src);
        }
        uint32_t bb = ab + ABUF;
#pragma unroll
        for (int i = 0; i < NBL; i++) {
            int s = tid + i * 256;
            uint32_t dst = bb + (uint32_t)((s >> 2) * RSTR + (s & 3) * 16);
            const __half* src = &Bt[(long)(n0 + (s >> 2)) * ldb + k0 + (s & 3) * 8];
            CP_ASYNC16(dst, src);
        }
    };

    // Prologue: ALWAYS commit NSTAGE-1 groups (empty groups when nchunks is small)
    // so the wait invariant "group c complete before chunk c compute" holds for any K.
#pragma unroll
    for (int c = 0; c < NSTAGE - 1; c++) {
        if (c < nchunks) issue(c);
        CP_COMMIT();
    }

    for (int c = 0; c < nchunks; c++) {
        CP_WAIT(NSTAGE - 2);
        __syncthreads();

        int nx = c + NSTAGE - 1;
        if (nx < nchunks) issue(nx);
        CP_COMMIT();

        uint32_t abuf = sbase + (c % NSTAGE) * BUFSZ;
        uint32_t bbuf = abuf + ABUF;
#pragma unroll
        for (int ks = 0; ks < 2; ks++) {
            uint32_t af[2][4], bf[NFR][2];
#pragma unroll
            for (int mt = 0; mt < 2; mt++) {
                uint32_t addr = abuf + (uint32_t)((wm * 32 + mt * 16 + (lane & 15)) * RSTR)
                              + ks * 32 + ((lane >> 4) << 4);
                ldm_x4(af[mt], addr);
            }
#pragma unroll
            for (int p = 0; p < NFR / 2; p++) {
                uint32_t rr4[4];
                uint32_t addr = bbuf + (uint32_t)((wn * (BN / 2) + p * 16 + (lane & 7) + ((lane >> 4) << 3)) * RSTR)
                              + ks * 32 + (((lane >> 3) & 1) << 4);
                ldm_x4(rr4, addr);
                bf[2 * p][0] = rr4[0]; bf[2 * p][1] = rr4[1];
                bf[2 * p + 1][0] = rr4[2]; bf[2 * p + 1][1] = rr4[3];
            }
#pragma unroll
            for (int mt = 0; mt < 2; mt++)
#pragma unroll
                for (int nt = 0; nt < NFR; nt++)
                    mma16816(acc[mt][nt], af[mt], bf[nt]);
        }
        __syncthreads();
    }

    // ---- epilogue: fragments -> smem (coalesce) -> global ----
    {
        float* ep = (float*)dynsmem;
        int qq = lane >> 2, rr = lane & 3;
#pragma unroll
        for (int mt = 0; mt < 2; mt++)
#pragma unroll
            for (int nt = 0; nt < NFR; nt++)
#pragma unroll
                for (int rg = 0; rg < 4; rg++) {
                    int row = wm * 32 + mt * 16 + qq + (rg >> 1) * 8;
                    int col = wn * (BN / 2) + nt * 8 + rr * 2 + (rg & 1);
                    int gn = n0 + col;
                    float v = acc[mt][nt][rg] * alpha;
                    if (bias && gn < Nstore) v += bias[gn];
                    if (act) v = 0.5f * v * (1.f + erff(v * 0.70710678118654752f));
                    ep[row * BNP + col] = v;
                }
        __syncthreads();

        if (!transC) {
            for (int idx = tid; idx < 128 * BN; idx += 256) {
                int r2 = idx / BN, c2 = idx % BN;
                int gn = n0 + c2;
                if (gn < Nstore) {
                    long gaddr = (long)(m0 + r2) * ldc + gn;
                    float v = ep[r2 * BNP + c2];
                    if (R) v += R[gaddr];
                    C[gaddr] = (CT)v;
                }
            }
        } else {
            // C layout: [b][h][hd][t]; m=(b,t), n=(h,hd)
            for (int idx = tid; idx < 128 * BN; idx += 256) {
                int r2 = idx & 127, c2 = idx >> 7;
                int gm = m0 + r2, gn = n0 + c2;
                int b = gm >> 10, t = gm & 1023;
                int hh = gn >> 6, hd = gn & 63;
                C[(((long)b * H_ + hh) * HD_ + hd) * T_ + t] = (CT)ep[r2 * BNP + c2];
            }
        }
    }
}

// ---------------- weight transpose+convert: in[K,N] fp32 -> out[N,K] half ----------------
__global__ void transpose_kernel(const float* __restrict__ in, __half* __restrict__ out,
                                 int Kd, int Nd, int Nout, long sIn, long sOut)
{
    __shared__ float t[32][33];
    int zz = blockIdx.z;
    in  += (long)zz * sIn;
    out += (long)zz * sOut;
    int n = blockIdx.x * 32 + threadIdx.x;
#pragma unroll
    for (int j = 0; j < 4; j++) {
        int k = blockIdx.y * 32 + threadIdx.y + j * 8;
        t[threadIdx.y + j * 8][threadIdx.x] = (n < Nd && k < Kd) ? in[(long)k * Nd + n] : 0.f;
    }
    __syncthreads();
#pragma unroll
    for (int j = 0; j < 4; j++) {
        int n2 = blockIdx.x * 32 + threadIdx.y + j * 8;
        int k2 = blockIdx.y * 32 + threadIdx.x;
        if (n2 < Nout && k2 < Kd) out[(long)n2 * Kd + k2] = __float2half(t[threadIdx.x][threadIdx.y + j * 8]);
    }
}

// ---------------- embedding ----------------
__global__ void embed_kernel(const int* __restrict__ idx, const float* __restrict__ tok,
                             const float* __restrict__ pos, float* __restrict__ x)
{
    long i = (long)blockIdx.x * 256 + threadIdx.x;
    if (i >= (long)NT * D_) return;
    int d = (int)(i % D_);
    long row = i / D_;
    int t = (int)(row % T_);
    x[i] = tok[(long)idx[row] * D_ + d] + pos[(long)t * D_ + d];
}

// ---------------- layernorm: fp32 in, half out ----------------
__global__ void layernorm_kernel(const float* __restrict__ x, const float* __restrict__ w,
                                 const float* __restrict__ b, __half* __restrict__ y)
{
    int r = blockIdx.x;
    const float* xr = x + (long)r * D_;
    __half* yr = y + (long)r * D_;
    __shared__ float s1[256], s2[256];
    int tid = threadIdx.x;
    float a = 0.f, sq = 0.f;
    for (int i = tid; i < D_; i += 256) { float v = xr[i]; a += v; sq += v * v; }
    s1[tid] = a; s2[tid] = sq; __syncthreads();
    for (int s = 128; s > 0; s >>= 1) {
        if (tid < s) { s1[tid] += s1[tid + s]; s2[tid] += s2[tid + s]; }
        __syncthreads();
    }
    float mu = s1[0] * (1.f / D_);
    float var = s2[0] * (1.f / D_) - mu * mu;
    float rstd = rsqrtf(var + 1e-5f);
    for (int i = tid; i < D_; i += 256)
        yr[i] = __float2half((xr[i] - mu) * rstd * w[i] + b[i]);
}

// ---------------- causal softmax: fp32 scores -> half probs ----------------
__global__ void softmax_causal_kernel(const float* __restrict__ scores, __half* __restrict__ p)
{
    int rrow = blockIdx.x;
    int qpos = rrow & (T_ - 1);
    const float4* row = (const float4*)(scores + (long)rrow * T_);
    __half2* prow = (__half2*)(p + (long)rrow * T_);
    int tid = threadIdx.x;
    float4 v = row[tid];
    int b0 = tid * 4;

    float x0 = (b0     <= qpos) ? v.x : -1e30f;
    float x1 = (b0 + 1 <= qpos) ? v.y : -1e30f;
    float x2 = (b0 + 2 <= qpos) ? v.z : -1e30f;
    float x3 = (b0 + 3 <= qpos) ? v.w : -1e30f;

    float m = fmaxf(fmaxf(x0, x1), fmaxf(x2, x3));
#pragma unroll
    for (int o = 16; o; o >>= 1) m = fmaxf(m, __shfl_xor_sync(0xffffffffu, m, o));

    __shared__ float sm[8], ss[8];
    int w = tid >> 5, ln = tid & 31;
    if (ln == 0) sm[w] = m;
    __syncthreads();
    m = sm[0];
#pragma unroll
    for (int i = 1; i < 8; i++) m = fmaxf(m, sm[i]);

    float e0 = expf(x0 - m), e1 = expf(x1 - m), e2 = expf(x2 - m), e3 = expf(x3 - m);
    float s = e0 + e1 + e2 + e3;
#pragma unroll
    for (int o = 16; o; o >>= 1) s += __shfl_xor_sync(0xffffffffu, s, o);
    if (ln == 0) ss[w] = s;
    __syncthreads();
    s = ss[0];
#pragma unroll
    for (int i = 1; i < 8; i++) s += ss[i];
    float inv = 1.f / s;

    prow[tid * 2]     = __floats2half2_rn(e0 * inv, e1 * inv);
    prow[tid * 2 + 1] = __floats2half2_rn(e2 * inv, e3 * inv);
}

// ---------------- NLL ----------------
__global__ void nll_kernel(const float* __restrict__ logits, const int* __restrict__ targets,
                           float* __restrict__ nll)
{
    int rrow = blockIdx.x;
    const float* row = logits + (long)rrow * V_;
    int tid = threadIdx.x;

    float m = -1e30f, s = 0.f;
    for (int i = tid; i < V_; i += 256) {
        float v = row[i];
        if (v > m) { s = s * expf(m - v); m = v; }
        s += expf(v - m);
    }
#pragma unroll
    for (int o = 16; o; o >>= 1) {
        float mo = __shfl_xor_sync(0xffffffffu, m, o);
        float so = __shfl_xor_sync(0xffffffffu, s, o);
        float mn = fmaxf(m, mo);
        s = s * expf(m - mn) + so * expf(mo - mn);
        m = mn;
    }
    __shared__ float smM[8], smS[8];
    if ((tid & 31) == 0) { smM[tid >> 5] = m; smS[tid >> 5] = s; }
    __syncthreads();
    if (tid == 0) {
        m = smM[0]; s = smS[0];
#pragma unroll
        for (int i = 1; i < 8; i++) {
            float mn = fmaxf(m, smM[i]);
            s = s * expf(m - mn) + smS[i] * expf(smM[i] - mn);
            m = mn;
        }
        float lse = m + logf(s);
        nll[rrow] = lse - row[targets[rrow]];
    }
}

__global__ void loss_reduce_kernel(const float* __restrict__ nll, float* __restrict__ out)
{
    __shared__ float red[256];
    int tid = threadIdx.x;
    float a = 0.f;
    for (int i = tid; i < NT; i += 256) a += nll[i];
    red[tid] = a; __syncthreads();
    for (int s = 128; s > 0; s >>= 1) { if (tid < s) red[tid] += red[tid + s]; __syncthreads(); }
    if (tid == 0) out[0] = red[0] * (1.f / NT);
}

// ---------------- host ----------------
#define SMEM128 81920   // max(4*(128+128)*80 = 81920, 128*129*4 = 66048)
#define SMEM64  61440   // max(4*(128+64)*80  = 61440, 128*65*4  = 33280)

extern "C" void kernel_launch(void* const* d_in, const int* in_sizes, int n_in,
                              void* d_out, int out_size)
{
    const float* tok_emb = (const float*)d_in[0];
    const float* pos_emb = (const float*)d_in[1];
    const float* ln1_w   = (const float*)d_in[2];
    const float* ln1_b   = (const float*)d_in[3];
    const float* ln2_w   = (const float*)d_in[4];
    const float* ln2_b   = (const float*)d_in[5];
    const float* wq      = (const float*)d_in[6];
    const float* wk      = (const float*)d_in[7];
    const float* wv      = (const float*)d_in[8];
    const float* wproj   = (const float*)d_in[9];
    const float* bproj   = (const float*)d_in[10];
    const float* w1      = (const float*)d_in[11];
    const float* b1      = (const float*)d_in[12];
    const float* w2      = (const float*)d_in[13];
    const float* b2      = (const float*)d_in[14];
    const float* lnf_w   = (const float*)d_in[15];
    const float* lnf_b   = (const float*)d_in[16];
    const float* lm_w    = (const float*)d_in[17];
    const float* lm_b    = (const float*)d_in[18];
    const int*   indexp  = (const int*)d_in[19];
    const int*   targets = (const int*)d_in[20];

    float* out = (float*)d_out;

    cudaFuncSetAttribute(gemm_h_kernel<128, float>,  cudaFuncAttributeMaxDynamicSharedMemorySize, SMEM128);
    cudaFuncSetAttribute(gemm_h_kernel<128, __half>, cudaFuncAttributeMaxDynamicSharedMemorySize, SMEM128);
    cudaFuncSetAttribute(gemm_h_kernel<64,  __half>, cudaFuncAttributeMaxDynamicSharedMemorySize, SMEM64);

    float *x, *scores, *nll;
    __half *h, *q, *kh, *vt, *att, *p, *mlp;
    __half *wqT, *wkT, *wvT, *wpT, *w1T, *w2T, *lmwT;
    cudaGetSymbolAddress((void**)&x,      g_x);
    cudaGetSymbolAddress((void**)&scores, g_scores);
    cudaGetSymbolAddress((void**)&nll,    g_nll);
    cudaGetSymbolAddress((void**)&h,      g_h);
    cudaGetSymbolAddress((void**)&q,      g_q);
    cudaGetSymbolAddress((void**)&kh,     g_k);
    cudaGetSymbolAddress((void**)&vt,     g_vt);
    cudaGetSymbolAddress((void**)&att,    g_att);
    cudaGetSymbolAddress((void**)&p,      g_p);
    cudaGetSymbolAddress((void**)&mlp,    g_mlp);
    cudaGetSymbolAddress((void**)&wqT,    g_wqT);
    cudaGetSymbolAddress((void**)&wkT,    g_wkT);
    cudaGetSymbolAddress((void**)&wvT,    g_wvT);
    cudaGetSymbolAddress((void**)&wpT,    g_wpT);
    cudaGetSymbolAddress((void**)&w1T,    g_w1T);
    cudaGetSymbolAddress((void**)&w2T,    g_w2T);
    cudaGetSymbolAddress((void**)&lmwT,   g_lmwT);

    // embeddings + weight transposes (fp32 -> half, K-major)
    {
        long total = (long)NT * D_;
        embed_kernel<<<(int)((total + 255) / 256), 256>>>(indexp, tok_emb, pos_emb, x);

        dim3 tb(32, 8);
        dim3 gdd(D_ / 32, D_ / 32, L_);
        transpose_kernel<<<gdd, tb>>>(wq,    wqT, D_, D_, D_, (long)D_ * D_, (long)D_ * D_);
        transpose_kernel<<<gdd, tb>>>(wk,    wkT, D_, D_, D_, (long)D_ * D_, (long)D_ * D_);
        transpose_kernel<<<gdd, tb>>>(wv,    wvT, D_, D_, D_, (long)D_ * D_, (long)D_ * D_);
        transpose_kernel<<<gdd, tb>>>(wproj, wpT, D_, D_, D_, (long)D_ * D_, (long)D_ * D_);
        dim3 g1(FF / 32, D_ / 32, L_);
        transpose_kernel<<<g1, tb>>>(w1, w1T, D_, FF, FF, (long)D_ * FF, (long)FF * D_);
        dim3 g2(D_ / 32, FF / 32, L_);
        transpose_kernel<<<g2, tb>>>(w2, w2T, FF, D_, D_, (long)FF * D_, (long)D_ * FF);
        dim3 g3(VPAD / 32, D_ / 32, 1);
        transpose_kernel<<<g3, tb>>>(lm_w, lmwT, D_, V_, VPAD, 0, 0);
    }

    const float scale = 1.0f / 8.0f;

    for (int l = 0; l < L_; l++) {
        const __half* wqT_l = wqT + (long)l * D_ * D_;
        const __half* wkT_l = wkT + (long)l * D_ * D_;
        const __half* wvT_l = wvT + (long)l * D_ * D_;
        const __half* wpT_l = wpT + (long)l * D_ * D_;
        const float*  bp_l  = bproj + (long)l * D_;
        const __half* w1T_l = w1T + (long)l * FF * D_;
        const float*  b1_l  = b1 + (long)l * FF;
        const __half* w2T_l = w2T + (long)l * D_ * FF;
        const float*  b2_l  = b2 + (long)l * D_;

        layernorm_kernel<<<NT, 256>>>(x, ln1_w + (long)l * D_, ln1_b + (long)l * D_, h);

        // q, k (half), vT (half, transposed layout)
        gemm_h_kernel<128, __half><<<dim3(D_ / 128, NT / 128, 1), 256, SMEM128>>>(
            h, wqT_l, nullptr, nullptr, q, NT, D_, D_, D_, D_, D_,
            0, 0, 0, 0, 0, 0, 1, 1.f, 0, 0);
        gemm_h_kernel<128, __half><<<dim3(D_ / 128, NT / 128, 1), 256, SMEM128>>>(
            h, wkT_l, nullptr, nullptr, kh, NT, D_, D_, D_, D_, D_,
            0, 0, 0, 0, 0, 0, 1, 1.f, 0, 0);
        gemm_h_kernel<128, __half><<<dim3(D_ / 128, NT / 128, 1), 256, SMEM128>>>(
            h, wvT_l, nullptr, nullptr, vt, NT, D_, D_, D_, D_, D_,
            0, 0, 0, 0, 0, 0, 1, 1.f, 0, 1);

        // scores = scale * Q @ K^T  (batch 48)
        gemm_h_kernel<128, float><<<dim3(T_ / 128, T_ / 128, B_ * H_), 256, SMEM128>>>(
            q, kh, nullptr, nullptr, scores, T_, T_, HD_, D_, D_, T_,
            (long)T_ * D_, 64, (long)T_ * D_, 64,
            (long)H_ * T_ * T_, (long)T_ * T_, H_, scale, 0, 0);

        softmax_causal_kernel<<<B_ * H_ * T_, 256>>>(scores, p);

        // att = P @ V  (A = p half, B = vT half; N=64)
        gemm_h_kernel<64, __half><<<dim3(1, T_ / 128, B_ * H_), 256, SMEM64>>>(
            p, vt, nullptr, nullptr, att, T_, HD_, T_, T_, T_, D_,
            (long)H_ * T_ * T_, (long)T_ * T_,
            (long)H_ * HD_ * T_, (long)HD_ * T_,
            (long)T_ * D_, 64, H_, 1.f, 0, 0);

        // x += att @ wproj + bproj
        gemm_h_kernel<128, float><<<dim3(D_ / 128, NT / 128, 1), 256, SMEM128>>>(
            att, wpT_l, bp_l, x, x, NT, D_, D_, D_, D_, D_,
            0, 0, 0, 0, 0, 0, 1, 1.f, 0, 0);

        layernorm_kernel<<<NT, 256>>>(x, ln2_w + (long)l * D_, ln2_b + (long)l * D_, h);

        // mlp = gelu(h @ w1 + b1)  (half out)
        gemm_h_kernel<128, __half><<<dim3(FF / 128, NT / 128, 1), 256, SMEM128>>>(
            h, w1T_l, b1_l, nullptr, mlp, NT, FF, D_, D_, D_, FF,
            0, 0, 0, 0, 0, 0, 1, 1.f, 1, 0);

        // x += mlp @ w2 + b2
        gemm_h_kernel<128, float><<<dim3(D_ / 128, NT / 128, 1), 256, SMEM128>>>(
            mlp, w2T_l, b2_l, x, x, NT, D_, FF, FF, FF, D_,
            0, 0, 0, 0, 0, 0, 1, 1.f, 0, 0);
    }

    layernorm_kernel<<<NT, 256>>>(x, lnf_w, lnf_b, h);

    long logits_elems = (long)NT * V_;
    if ((long)out_size >= logits_elems) {
        gemm_h_kernel<128, float><<<dim3(VPAD / 128, NT / 128, 1), 256, SMEM128>>>(
            h, lmwT, lm_b, nullptr, out, NT, V_, D_, D_, D_, V_,
            0, 0, 0, 0, 0, 0, 1, 1.f, 0, 0);

        nll_kernel<<<NT, 256>>>(out, targets, nll);
        if ((long)out_size >= logits_elems + 1) {
            loss_reduce_kernel<<<1, 256>>>(nll, out + logits_elems);
        }
    }
}

// round 10
// speedup vs baseline: 7.4626x; 1.1912x over previous
#include <cuda_runtime.h>
#include <cuda_fp16.h>
#include <math.h>
#include <stdint.h>

// ---------------- problem constants ----------------
#define B_  4
#define T_  1024
#define D_  768
#define H_  12
#define HD_ 64
#define L_  6
#define V_  50257
#define VPAD 50304
#define NT  4096
#define FF  3072

// ---------------- scratch ----------------
__device__ float  g_x  [NT * D_];
__device__ float  g_nll[NT];
__device__ __half g_h  [NT * D_];
__device__ __half g_q  [NT * D_];
__device__ __half g_k  [NT * D_];
__device__ __half g_vt [NT * D_];            // [B][H][HD][T]
__device__ __half g_att[NT * D_];
__device__ __half g_mlp[NT * FF];
__device__ __half g_wqT [L_ * D_ * D_];
__device__ __half g_wkT [L_ * D_ * D_];
__device__ __half g_wvT [L_ * D_ * D_];
__device__ __half g_wpT [L_ * D_ * D_];
__device__ __half g_w1T [L_ * FF * D_];      // [FF][D]
__device__ __half g_w2T [L_ * D_ * FF];      // [D][FF]
__device__ __half g_lmwT[(size_t)VPAD * D_];

// ---------------- helpers ----------------
__device__ __forceinline__ uint32_t smem_u32(const void* p) {
    uint32_t a;
    asm("{ .reg .u64 t; cvta.to.shared.u64 t, %1; cvt.u32.u64 %0, t; }" : "=r"(a) : "l"(p));
    return a;
}
__device__ __forceinline__ void ldm_x4(uint32_t* r, uint32_t addr) {
    asm volatile("ldmatrix.sync.aligned.m8n8.x4.shared.b16 {%0,%1,%2,%3}, [%4];"
        : "=r"(r[0]), "=r"(r[1]), "=r"(r[2]), "=r"(r[3]) : "r"(addr));
}
__device__ __forceinline__ void mma16816(float* c, const uint32_t* a, const uint32_t* b) {
    asm volatile(
        "mma.sync.aligned.m16n8k16.row.col.f32.f16.f16.f32 "
        "{%0,%1,%2,%3},{%4,%5,%6,%7},{%8,%9},{%0,%1,%2,%3};"
        : "+f"(c[0]), "+f"(c[1]), "+f"(c[2]), "+f"(c[3])
        : "r"(a[0]), "r"(a[1]), "r"(a[2]), "r"(a[3]), "r"(b[0]), "r"(b[1]));
}
__device__ __forceinline__ uint32_t pack_h2(float x, float y) {
    __half2 h = __floats2half2_rn(x, y);
    return *reinterpret_cast<uint32_t*>(&h);
}
#define CP_ASYNC16(dst, src) \
    asm volatile("cp.async.cg.shared.global [%0], [%1], 16;" :: "r"(dst), "l"(src) : "memory")
#define CP_COMMIT() asm volatile("cp.async.commit_group;" ::: "memory")
#define CP_WAIT(n)  asm volatile("cp.async.wait_group %0;" :: "n"(n) : "memory")

// ---------------- fp16 mma.sync GEMM with cp.async 4-stage pipeline ----------------
#define BKC 32
#define RSTR 80
#define NSTAGE 4

template<int BN, typename CT>
__global__ __launch_bounds__(256, 2)
void gemm_h_kernel(const __half* __restrict__ A, const __half* __restrict__ Bt,
                   const float* __restrict__ bias, const float* __restrict__ R,
                   CT* __restrict__ C,
                   int M, int Nstore, int K, int lda, int ldb, int ldc,
                   long sAb, long sAh, long sBb, long sBh, long sCb, long sCh,
                   int batchH, float alpha, int act, int transC, int swapxy)
{
    extern __shared__ __align__(16) char dynsmem[];
    constexpr int ABUF  = 128 * RSTR;
    constexpr int BBUF  = BN * RSTR;
    constexpr int BUFSZ = ABUF + BBUF;
    constexpr int NFR   = BN / 16;
    constexpr int NBL   = BN / 64;
    constexpr int BNP   = BN + 1;

    uint32_t sbase = smem_u32(dynsmem);
    int tid = threadIdx.x;
    int lane = tid & 31, warp = tid >> 5;
    int wm = warp & 3, wn = warp >> 2;

    int z  = blockIdx.z;
    int bz = z / batchH, hz = z % batchH;
    A  += (long)bz * sAb + (long)hz * sAh;
    Bt += (long)bz * sBb + (long)hz * sBh;
    C  += (long)bz * sCb + (long)hz * sCh;
    if (R) R += (long)bz * sCb + (long)hz * sCh;

    int bxn = swapxy ? blockIdx.y : blockIdx.x;
    int bym = swapxy ? blockIdx.x : blockIdx.y;
    int m0 = bym * 128;
    int n0 = bxn * BN;

    float acc[2][NFR][4];
#pragma unroll
    for (int mt = 0; mt < 2; mt++)
#pragma unroll
        for (int nt = 0; nt < NFR; nt++)
#pragma unroll
            for (int rg = 0; rg < 4; rg++) acc[mt][nt][rg] = 0.f;

    int nchunks = K / BKC;

    auto issue = [&](int c) {
        int k0 = c * BKC;
        uint32_t ab = sbase + (c % NSTAGE) * BUFSZ;
#pragma unroll
        for (int i = 0; i < 2; i++) {
            int s = tid + i * 256;
            uint32_t dst = ab + (uint32_t)((s >> 2) * RSTR + (s & 3) * 16);
            const __half* src = &A[(long)(m0 + (s >> 2)) * lda + k0 + (s & 3) * 8];
            CP_ASYNC16(dst, src);
        }
        uint32_t bb = ab + ABUF;
#pragma unroll
        for (int i = 0; i < NBL; i++) {
            int s = tid + i * 256;
            uint32_t dst = bb + (uint32_t)((s >> 2) * RSTR + (s & 3) * 16);
            const __half* src = &Bt[(long)(n0 + (s >> 2)) * ldb + k0 + (s & 3) * 8];
            CP_ASYNC16(dst, src);
        }
    };

#pragma unroll
    for (int c = 0; c < NSTAGE - 1; c++) {
        if (c < nchunks) issue(c);
        CP_COMMIT();
    }

    for (int c = 0; c < nchunks; c++) {
        CP_WAIT(NSTAGE - 2);
        __syncthreads();

        int nx = c + NSTAGE - 1;
        if (nx < nchunks) issue(nx);
        CP_COMMIT();

        uint32_t abuf = sbase + (c % NSTAGE) * BUFSZ;
        uint32_t bbuf = abuf + ABUF;
#pragma unroll
        for (int ks = 0; ks < 2; ks++) {
            uint32_t af[2][4], bf[NFR][2];
#pragma unroll
            for (int mt = 0; mt < 2; mt++) {
                uint32_t addr = abuf + (uint32_t)((wm * 32 + mt * 16 + (lane & 15)) * RSTR)
                              + ks * 32 + ((lane >> 4) << 4);
                ldm_x4(af[mt], addr);
            }
#pragma unroll
            for (int p = 0; p < NFR / 2; p++) {
                uint32_t rr4[4];
                uint32_t addr = bbuf + (uint32_t)((wn * (BN / 2) + p * 16 + (lane & 7) + ((lane >> 4) << 3)) * RSTR)
                              + ks * 32 + (((lane >> 3) & 1) << 4);
                ldm_x4(rr4, addr);
                bf[2 * p][0] = rr4[0]; bf[2 * p][1] = rr4[1];
                bf[2 * p + 1][0] = rr4[2]; bf[2 * p + 1][1] = rr4[3];
            }
#pragma unroll
            for (int mt = 0; mt < 2; mt++)
#pragma unroll
                for (int nt = 0; nt < NFR; nt++)
                    mma16816(acc[mt][nt], af[mt], bf[nt]);
        }
        __syncthreads();
    }

    // ---- epilogue ----
    {
        float* ep = (float*)dynsmem;
        int qq = lane >> 2, rr = lane & 3;
#pragma unroll
        for (int mt = 0; mt < 2; mt++)
#pragma unroll
            for (int nt = 0; nt < NFR; nt++)
#pragma unroll
                for (int rg = 0; rg < 4; rg++) {
                    int row = wm * 32 + mt * 16 + qq + (rg >> 1) * 8;
                    int col = wn * (BN / 2) + nt * 8 + rr * 2 + (rg & 1);
                    int gn = n0 + col;
                    float v = acc[mt][nt][rg] * alpha;
                    if (bias && gn < Nstore) v += bias[gn];
                    if (act) v = 0.5f * v * (1.f + erff(v * 0.70710678118654752f));
                    ep[row * BNP + col] = v;
                }
        __syncthreads();

        if (!transC) {
            for (int idx = tid; idx < 128 * BN; idx += 256) {
                int r2 = idx / BN, c2 = idx % BN;
                int gn = n0 + c2;
                if (gn < Nstore) {
                    long gaddr = (long)(m0 + r2) * ldc + gn;
                    float v = ep[r2 * BNP + c2];
                    if (R) v += R[gaddr];
                    C[gaddr] = (CT)v;
                }
            }
        } else {
            for (int idx = tid; idx < 128 * BN; idx += 256) {
                int r2 = idx & 127, c2 = idx >> 7;
                int gm = m0 + r2, gn = n0 + c2;
                int b = gm >> 10, t = gm & 1023;
                int hh = gn >> 6, hd = gn & 63;
                C[(((long)b * H_ + hh) * HD_ + hd) * T_ + t] = (CT)ep[r2 * BNP + c2];
            }
        }
    }
}

// ---------------- flash attention: QK^T + causal softmax + PV fused ----------------
// grid (T/128, B*H), 256 threads = 8 warps, each warp owns 16 q-rows.
#define FRS 144   // 64 halves = 128B data + 16B pad (9*16B: conflict-free)
#define FQ_BYTES  (128 * FRS)          // 18432
#define FKV_BYTES (64 * FRS)           // 9216
#define FSTAGE    (2 * FKV_BYTES)      // K + V per stage
#define FSMEM     (FQ_BYTES + 2 * FSTAGE)  // 55296

__global__ __launch_bounds__(256, 1)
void flash_kernel(const __half* __restrict__ Qg, const __half* __restrict__ Kg,
                  const __half* __restrict__ Vt, __half* __restrict__ Og)
{
    extern __shared__ __align__(16) char fsm[];
    uint32_t sbase = smem_u32(fsm);
    int tid = threadIdx.x, lane = tid & 31, w = tid >> 5;
    int qq = lane >> 2, rr = lane & 3;

    int qi = blockIdx.x, bh = blockIdx.y;
    int b = bh / H_, h = bh % H_;
    int q0 = qi * 128;

    const __half* qptr = Qg + ((long)b * T_ + q0) * D_ + h * HD_;
    const __half* kptr = Kg + (long)b * T_ * D_ + h * HD_;
    const __half* vptr = Vt + (long)bh * HD_ * T_;

    uint32_t qb = sbase;

    // load Q tile (128 rows x 64 halves = 128 rows x 8 chunks of 16B)
    {
#pragma unroll
        for (int i = 0; i < 4; i++) {
            int s = tid + i * 256;                 // 1024 slots: row = s>>3, chunk = s&7
            uint32_t dst = qb + (uint32_t)((s >> 3) * FRS + (s & 7) * 16);
            CP_ASYNC16(dst, qptr + (long)(s >> 3) * D_ + (s & 7) * 8);
        }
        CP_COMMIT();
    }

    int nkv = 2 * qi + 2;

    auto issue_kv = [&](int j) {
        uint32_t kb = sbase + FQ_BYTES + (j & 1) * FSTAGE;
        uint32_t vb = kb + FKV_BYTES;
        int j0 = j * 64;
        // K and V tiles: 64 rows x 8 chunks = 512 transfers each
#pragma unroll
        for (int i = 0; i < 2; i++) {
            int s = tid + i * 256;                 // row = s>>3, chunk = s&7
            int row = s >> 3, c16 = s & 7;
            CP_ASYNC16(kb + (uint32_t)(row * FRS + c16 * 16),
                       kptr + (long)(j0 + row) * D_ + c16 * 8);
            CP_ASYNC16(vb + (uint32_t)(row * FRS + c16 * 16),
                       vptr + (long)row * T_ + j0 + c16 * 8);
        }
    };

    issue_kv(0);
    CP_COMMIT();

    float m0 = -1e30f, m1 = -1e30f, l0 = 0.f, l1 = 0.f;
    float o[8][4];
#pragma unroll
    for (int nt = 0; nt < 8; nt++)
#pragma unroll
        for (int e = 0; e < 4; e++) o[nt][e] = 0.f;

    uint32_t aq[4][4];

    for (int j = 0; j < nkv; j++) {
        __syncthreads();                       // all warps done with stage (j+1)&1 from iter j-1
        if (j + 1 < nkv) issue_kv(j + 1);
        CP_COMMIT();
        CP_WAIT(1);                            // tile j (and Q) complete
        __syncthreads();

        if (j == 0) {
#pragma unroll
            for (int ks = 0; ks < 4; ks++) {
                uint32_t addr = qb + (uint32_t)((w * 16 + (lane & 15)) * FRS)
                              + ks * 32 + ((lane >> 4) << 4);
                ldm_x4(aq[ks], addr);
            }
        }

        uint32_t kb = sbase + FQ_BYTES + (j & 1) * FSTAGE;
        uint32_t vb = kb + FKV_BYTES;

        // ---- S = Q @ K^T ----
        float sacc[8][4];
#pragma unroll
        for (int nt = 0; nt < 8; nt++)
#pragma unroll
            for (int e = 0; e < 4; e++) sacc[nt][e] = 0.f;

#pragma unroll
        for (int ks = 0; ks < 4; ks++) {
            uint32_t bf[8][2];
#pragma unroll
            for (int p = 0; p < 4; p++) {
                uint32_t r4[4];
                uint32_t addr = kb + (uint32_t)((p * 16 + (lane & 7) + ((lane >> 4) << 3)) * FRS)
                              + ks * 32 + (((lane >> 3) & 1) << 4);
                ldm_x4(r4, addr);
                bf[2 * p][0] = r4[0]; bf[2 * p][1] = r4[1];
                bf[2 * p + 1][0] = r4[2]; bf[2 * p + 1][1] = r4[3];
            }
#pragma unroll
            for (int nt = 0; nt < 8; nt++)
                mma16816(sacc[nt], aq[ks], bf[nt]);
        }

        // ---- scale + causal mask + online softmax ----
        int j0 = j * 64;
        int rowg0 = q0 + w * 16 + qq;
        int rowg1 = rowg0 + 8;
        bool needmask = (j >= nkv - 2);

        float rm0 = -1e30f, rm1 = -1e30f;
#pragma unroll
        for (int nt = 0; nt < 8; nt++) {
            int cb = j0 + nt * 8 + rr * 2;
            float s0 = sacc[nt][0] * 0.125f;
            float s1 = sacc[nt][1] * 0.125f;
            float s2 = sacc[nt][2] * 0.125f;
            float s3 = sacc[nt][3] * 0.125f;
            if (needmask) {
                if (cb     > rowg0) s0 = -1e30f;
                if (cb + 1 > rowg0) s1 = -1e30f;
                if (cb     > rowg1) s2 = -1e30f;
                if (cb + 1 > rowg1) s3 = -1e30f;
            }
            sacc[nt][0] = s0; sacc[nt][1] = s1; sacc[nt][2] = s2; sacc[nt][3] = s3;
            rm0 = fmaxf(rm0, fmaxf(s0, s1));
            rm1 = fmaxf(rm1, fmaxf(s2, s3));
        }
#pragma unroll
        for (int od = 1; od <= 2; od <<= 1) {
            rm0 = fmaxf(rm0, __shfl_xor_sync(0xffffffffu, rm0, od));
            rm1 = fmaxf(rm1, __shfl_xor_sync(0xffffffffu, rm1, od));
        }
        float mn0 = fmaxf(m0, rm0), mn1 = fmaxf(m1, rm1);
        float c0 = expf(m0 - mn0), c1 = expf(m1 - mn1);

        float rs0 = 0.f, rs1 = 0.f;
#pragma unroll
        for (int nt = 0; nt < 8; nt++) {
            float p0 = expf(sacc[nt][0] - mn0);
            float p1 = expf(sacc[nt][1] - mn0);
            float p2 = expf(sacc[nt][2] - mn1);
            float p3 = expf(sacc[nt][3] - mn1);
            sacc[nt][0] = p0; sacc[nt][1] = p1; sacc[nt][2] = p2; sacc[nt][3] = p3;
            rs0 += p0 + p1; rs1 += p2 + p3;
        }
#pragma unroll
        for (int od = 1; od <= 2; od <<= 1) {
            rs0 += __shfl_xor_sync(0xffffffffu, rs0, od);
            rs1 += __shfl_xor_sync(0xffffffffu, rs1, od);
        }
        l0 = l0 * c0 + rs0;
        l1 = l1 * c1 + rs1;
        m0 = mn0; m1 = mn1;

#pragma unroll
        for (int nt = 0; nt < 8; nt++) {
            o[nt][0] *= c0; o[nt][1] *= c0;
            o[nt][2] *= c1; o[nt][3] *= c1;
        }

        // ---- pack P to A-frags (FA2 repack, no shuffles) ----
        uint32_t ap[4][4];
#pragma unroll
        for (int ks2 = 0; ks2 < 4; ks2++) {
            ap[ks2][0] = pack_h2(sacc[2 * ks2][0],     sacc[2 * ks2][1]);
            ap[ks2][1] = pack_h2(sacc[2 * ks2][2],     sacc[2 * ks2][3]);
            ap[ks2][2] = pack_h2(sacc[2 * ks2 + 1][0], sacc[2 * ks2 + 1][1]);
            ap[ks2][3] = pack_h2(sacc[2 * ks2 + 1][2], sacc[2 * ks2 + 1][3]);
        }

        // ---- O += P @ V ----
#pragma unroll
        for (int ks2 = 0; ks2 < 4; ks2++) {
            uint32_t bf[8][2];
#pragma unroll
            for (int p = 0; p < 4; p++) {
                uint32_t r4[4];
                uint32_t addr = vb + (uint32_t)((p * 16 + (lane & 7) + ((lane >> 4) << 3)) * FRS)
                              + ks2 * 32 + (((lane >> 3) & 1) << 4);
                ldm_x4(r4, addr);
                bf[2 * p][0] = r4[0]; bf[2 * p][1] = r4[1];
                bf[2 * p + 1][0] = r4[2]; bf[2 * p + 1][1] = r4[3];
            }
#pragma unroll
            for (int nt = 0; nt < 8; nt++)
                mma16816(o[nt], ap[ks2], bf[nt]);
        }
    }

    // ---- normalize + write out ----
    float inv0 = 1.f / l0, inv1 = 1.f / l1;
    long obase = ((long)b * T_ + q0 + w * 16) * D_ + h * HD_;
#pragma unroll
    for (int nt = 0; nt < 8; nt++) {
        int col = nt * 8 + rr * 2;
        *(__half2*)&Og[obase + (long)qq * D_ + col] =
            __floats2half2_rn(o[nt][0] * inv0, o[nt][1] * inv0);
        *(__half2*)&Og[obase + (long)(qq + 8) * D_ + col] =
            __floats2half2_rn(o[nt][2] * inv1, o[nt][3] * inv1);
    }
}

// ---------------- weight transpose+convert ----------------
__global__ void transpose_kernel(const float* __restrict__ in, __half* __restrict__ out,
                                 int Kd, int Nd, int Nout, long sIn, long sOut)
{
    __shared__ float t[32][33];
    int zz = blockIdx.z;
    in  += (long)zz * sIn;
    out += (long)zz * sOut;
    int n = blockIdx.x * 32 + threadIdx.x;
#pragma unroll
    for (int j = 0; j < 4; j++) {
        int k = blockIdx.y * 32 + threadIdx.y + j * 8;
        t[threadIdx.y + j * 8][threadIdx.x] = (n < Nd && k < Kd) ? in[(long)k * Nd + n] : 0.f;
    }
    __syncthreads();
#pragma unroll
    for (int j = 0; j < 4; j++) {
        int n2 = blockIdx.x * 32 + threadIdx.y + j * 8;
        int k2 = blockIdx.y * 32 + threadIdx.x;
        if (n2 < Nout && k2 < Kd) out[(long)n2 * Kd + k2] = __float2half(t[threadIdx.x][threadIdx.y + j * 8]);
    }
}

// ---------------- embedding ----------------
__global__ void embed_kernel(const int* __restrict__ idx, const float* __restrict__ tok,
                             const float* __restrict__ pos, float* __restrict__ x)
{
    long i = (long)blockIdx.x * 256 + threadIdx.x;
    if (i >= (long)NT * D_) return;
    int d = (int)(i % D_);
    long row = i / D_;
    int t = (int)(row % T_);
    x[i] = tok[(long)idx[row] * D_ + d] + pos[(long)t * D_ + d];
}

// ---------------- layernorm: fp32 in, half out ----------------
__global__ void layernorm_kernel(const float* __restrict__ x, const float* __restrict__ w,
                                 const float* __restrict__ b, __half* __restrict__ y)
{
    int r = blockIdx.x;
    const float* xr = x + (long)r * D_;
    __half* yr = y + (long)r * D_;
    __shared__ float s1[256], s2[256];
    int tid = threadIdx.x;
    float a = 0.f, sq = 0.f;
    for (int i = tid; i < D_; i += 256) { float v = xr[i]; a += v; sq += v * v; }
    s1[tid] = a; s2[tid] = sq; __syncthreads();
    for (int s = 128; s > 0; s >>= 1) {
        if (tid < s) { s1[tid] += s1[tid + s]; s2[tid] += s2[tid + s]; }
        __syncthreads();
    }
    float mu = s1[0] * (1.f / D_);
    float var = s2[0] * (1.f / D_) - mu * mu;
    float rstd = rsqrtf(var + 1e-5f);
    for (int i = tid; i < D_; i += 256)
        yr[i] = __float2half((xr[i] - mu) * rstd * w[i] + b[i]);
}

// ---------------- NLL ----------------
__global__ void nll_kernel(const float* __restrict__ logits, const int* __restrict__ targets,
                           float* __restrict__ nll)
{
    int rrow = blockIdx.x;
    const float* row = logits + (long)rrow * V_;
    int tid = threadIdx.x;

    float m = -1e30f, s = 0.f;
    for (int i = tid; i < V_; i += 256) {
        float v = row[i];
        if (v > m) { s = s * expf(m - v); m = v; }
        s += expf(v - m);
    }
#pragma unroll
    for (int o = 16; o; o >>= 1) {
        float mo = __shfl_xor_sync(0xffffffffu, m, o);
        float so = __shfl_xor_sync(0xffffffffu, s, o);
        float mn = fmaxf(m, mo);
        s = s * expf(m - mn) + so * expf(mo - mn);
        m = mn;
    }
    __shared__ float smM[8], smS[8];
    if ((tid & 31) == 0) { smM[tid >> 5] = m; smS[tid >> 5] = s; }
    __syncthreads();
    if (tid == 0) {
        m = smM[0]; s = smS[0];
#pragma unroll
        for (int i = 1; i < 8; i++) {
            float mn = fmaxf(m, smM[i]);
            s = s * expf(m - mn) + smS[i] * expf(smM[i] - mn);
            m = mn;
        }
        float lse = m + logf(s);
        nll[rrow] = lse - row[targets[rrow]];
    }
}

__global__ void loss_reduce_kernel(const float* __restrict__ nll, float* __restrict__ out)
{
    __shared__ float red[256];
    int tid = threadIdx.x;
    float a = 0.f;
    for (int i = tid; i < NT; i += 256) a += nll[i];
    red[tid] = a; __syncthreads();
    for (int s = 128; s > 0; s >>= 1) { if (tid < s) red[tid] += red[tid + s]; __syncthreads(); }
    if (tid == 0) out[0] = red[0] * (1.f / NT);
}

// ---------------- host ----------------
#define SMEM128 81920

extern "C" void kernel_launch(void* const* d_in, const int* in_sizes, int n_in,
                              void* d_out, int out_size)
{
    const float* tok_emb = (const float*)d_in[0];
    const float* pos_emb = (const float*)d_in[1];
    const float* ln1_w   = (const float*)d_in[2];
    const float* ln1_b   = (const float*)d_in[3];
    const float* ln2_w   = (const float*)d_in[4];
    const float* ln2_b   = (const float*)d_in[5];
    const float* wq      = (const float*)d_in[6];
    const float* wk      = (const float*)d_in[7];
    const float* wv      = (const float*)d_in[8];
    const float* wproj   = (const float*)d_in[9];
    const float* bproj   = (const float*)d_in[10];
    const float* w1      = (const float*)d_in[11];
    const float* b1      = (const float*)d_in[12];
    const float* w2      = (const float*)d_in[13];
    const float* b2      = (const float*)d_in[14];
    const float* lnf_w   = (const float*)d_in[15];
    const float* lnf_b   = (const float*)d_in[16];
    const float* lm_w    = (const float*)d_in[17];
    const float* lm_b    = (const float*)d_in[18];
    const int*   indexp  = (const int*)d_in[19];
    const int*   targets = (const int*)d_in[20];

    float* out = (float*)d_out;

    cudaFuncSetAttribute(gemm_h_kernel<128, float>,  cudaFuncAttributeMaxDynamicSharedMemorySize, SMEM128);
    cudaFuncSetAttribute(gemm_h_kernel<128, __half>, cudaFuncAttributeMaxDynamicSharedMemorySize, SMEM128);
    cudaFuncSetAttribute(flash_kernel, cudaFuncAttributeMaxDynamicSharedMemorySize, FSMEM);

    float *x, *nll;
    __half *h, *q, *kh, *vt, *att, *mlp;
    __half *wqT, *wkT, *wvT, *wpT, *w1T, *w2T, *lmwT;
    cudaGetSymbolAddress((void**)&x,      g_x);
    cudaGetSymbolAddress((void**)&nll,    g_nll);
    cudaGetSymbolAddress((void**)&h,      g_h);
    cudaGetSymbolAddress((void**)&q,      g_q);
    cudaGetSymbolAddress((void**)&kh,     g_k);
    cudaGetSymbolAddress((void**)&vt,     g_vt);
    cudaGetSymbolAddress((void**)&att,    g_att);
    cudaGetSymbolAddress((void**)&mlp,    g_mlp);
    cudaGetSymbolAddress((void**)&wqT,    g_wqT);
    cudaGetSymbolAddress((void**)&wkT,    g_wkT);
    cudaGetSymbolAddress((void**)&wvT,    g_wvT);
    cudaGetSymbolAddress((void**)&wpT,    g_wpT);
    cudaGetSymbolAddress((void**)&w1T,    g_w1T);
    cudaGetSymbolAddress((void**)&w2T,    g_w2T);
    cudaGetSymbolAddress((void**)&lmwT,   g_lmwT);

    // embeddings + weight transposes (fp32 -> half, K-major)
    {
        long total = (long)NT * D_;
        embed_kernel<<<(int)((total + 255) / 256), 256>>>(indexp, tok_emb, pos_emb, x);

        dim3 tb(32, 8);
        dim3 gdd(D_ / 32, D_ / 32, L_);
        transpose_kernel<<<gdd, tb>>>(wq,    wqT, D_, D_, D_, (long)D_ * D_, (long)D_ * D_);
        transpose_kernel<<<gdd, tb>>>(wk,    wkT, D_, D_, D_, (long)D_ * D_, (long)D_ * D_);
        transpose_kernel<<<gdd, tb>>>(wv,    wvT, D_, D_, D_, (long)D_ * D_, (long)D_ * D_);
        transpose_kernel<<<gdd, tb>>>(wproj, wpT, D_, D_, D_, (long)D_ * D_, (long)D_ * D_);
        dim3 g1(FF / 32, D_ / 32, L_);
        transpose_kernel<<<g1, tb>>>(w1, w1T, D_, FF, FF, (long)D_ * FF, (long)FF * D_);
        dim3 g2(D_ / 32, FF / 32, L_);
        transpose_kernel<<<g2, tb>>>(w2, w2T, FF, D_, D_, (long)FF * D_, (long)D_ * FF);
        dim3 g3(VPAD / 32, D_ / 32, 1);
        transpose_kernel<<<g3, tb>>>(lm_w, lmwT, D_, V_, VPAD, 0, 0);
    }

    for (int l = 0; l < L_; l++) {
        const __half* wqT_l = wqT + (long)l * D_ * D_;
        const __half* wkT_l = wkT + (long)l * D_ * D_;
        const __half* wvT_l = wvT + (long)l * D_ * D_;
        const __half* wpT_l = wpT + (long)l * D_ * D_;
        const float*  bp_l  = bproj + (long)l * D_;
        const __half* w1T_l = w1T + (long)l * FF * D_;
        const float*  b1_l  = b1 + (long)l * FF;
        const __half* w2T_l = w2T + (long)l * D_ * FF;
        const float*  b2_l  = b2 + (long)l * D_;

        layernorm_kernel<<<NT, 256>>>(x, ln1_w + (long)l * D_, ln1_b + (long)l * D_, h);

        gemm_h_kernel<128, __half><<<dim3(D_ / 128, NT / 128, 1), 256, SMEM128>>>(
            h, wqT_l, nullptr, nullptr, q, NT, D_, D_, D_, D_, D_,
            0, 0, 0, 0, 0, 0, 1, 1.f, 0, 0, 0);
        gemm_h_kernel<128, __half><<<dim3(D_ / 128, NT / 128, 1), 256, SMEM128>>>(
            h, wkT_l, nullptr, nullptr, kh, NT, D_, D_, D_, D_, D_,
            0, 0, 0, 0, 0, 0, 1, 1.f, 0, 0, 0);
        gemm_h_kernel<128, __half><<<dim3(D_ / 128, NT / 128, 1), 256, SMEM128>>>(
            h, wvT_l, nullptr, nullptr, vt, NT, D_, D_, D_, D_, D_,
            0, 0, 0, 0, 0, 0, 1, 1.f, 0, 1, 0);

        // fused attention: att = softmax(scale * Q K^T, causal) @ V
        flash_kernel<<<dim3(T_ / 128, B_ * H_), 256, FSMEM>>>(q, kh, vt, att);

        // x += att @ wproj + bproj
        gemm_h_kernel<128, float><<<dim3(D_ / 128, NT / 128, 1), 256, SMEM128>>>(
            att, wpT_l, bp_l, x, x, NT, D_, D_, D_, D_, D_,
            0, 0, 0, 0, 0, 0, 1, 1.f, 0, 0, 0);

        layernorm_kernel<<<NT, 256>>>(x, ln2_w + (long)l * D_, ln2_b + (long)l * D_, h);

        gemm_h_kernel<128, __half><<<dim3(FF / 128, NT / 128, 1), 256, SMEM128>>>(
            h, w1T_l, b1_l, nullptr, mlp, NT, FF, D_, D_, D_, FF,
            0, 0, 0, 0, 0, 0, 1, 1.f, 1, 0, 0);

        gemm_h_kernel<128, float><<<dim3(D_ / 128, NT / 128, 1), 256, SMEM128>>>(
            mlp, w2T_l, b2_l, x, x, NT, D_, FF, FF, FF, D_,
            0, 0, 0, 0, 0, 0, 1, 1.f, 0, 0, 0);
    }

    layernorm_kernel<<<NT, 256>>>(x, lnf_w, lnf_b, h);

    long logits_elems = (long)NT * V_;
    if ((long)out_size >= logits_elems) {
        // lm_head with swapped grid (m fastest) for B reuse in L2
        gemm_h_kernel<128, float><<<dim3(NT / 128, VPAD / 128, 1), 256, SMEM128>>>(
            h, lmwT, lm_b, nullptr, out, NT, V_, D_, D_, D_, V_,
            0, 0, 0, 0, 0, 0, 1, 1.f, 0, 0, 1);

        nll_kernel<<<NT, 256>>>(out, targets, nll);
        if ((long)out_size >= logits_elems + 1) {
            loss_reduce_kernel<<<1, 256>>>(nll, out + logits_elems);
        }
    }
}